// round 10
// baseline (speedup 1.0000x reference)
#include <cuda_runtime.h>
#include <cuda_fp16.h>
#include <cstdint>

// Shapes (fixed per reference setup_inputs)
#define B 2
#define S 512
#define T 512
#define D 256
#define H 128
#define BS (B*S)        // 1024
#define BT (B*T)        // 1024

#define PAD 136         // padded row stride (elems) for conflict-free ldmatrix

// Scratch (device globals; no allocation allowed)
__device__ float g_src[BS * H];       // LN(source) @ W_su + b_su (fp32)
__device__ float g_A  [BS * H];       // g_src @ W1_s + b1
__device__ float g_C  [BT * H];       // g_tgt @ W1_t
__device__ __half g_th [BT * H];      // fp16 target proj

// ---------------------------------------------------------------------------
// Stage 1: per-row layernorm + projection + W1_s / W1_t projection.
// ---------------------------------------------------------------------------
__global__ __launch_bounds__(256) void norm_proj_kernel(
    const float* __restrict__ sv, const float* __restrict__ tv,
    const float* __restrict__ sng, const float* __restrict__ snb,
    const float* __restrict__ tng, const float* __restrict__ tnb,
    const float* __restrict__ Wsu, const float* __restrict__ bsu,
    const float* __restrict__ Wtp, const float* __restrict__ btp,
    const float* __restrict__ W1,  const float* __restrict__ b1)
{
    __shared__ float xn[D];
    __shared__ float pr[H];
    __shared__ float r1[8], r2[8];

    const int r = blockIdx.x;
    const bool is_src = (r < BS);
    const int row = is_src ? r : r - BS;
    const int tid = threadIdx.x;

    const float* x    = (is_src ? sv : tv) + row * D;
    const float* gv   = is_src ? sng : tng;
    const float* bv   = is_src ? snb : tnb;
    const float* W    = is_src ? Wsu : Wtp;
    const float* bias = is_src ? bsu : btp;

    float v = x[tid];
    float s1 = v, s2 = v * v;
    #pragma unroll
    for (int m = 16; m; m >>= 1) {
        s1 += __shfl_xor_sync(0xffffffffu, s1, m);
        s2 += __shfl_xor_sync(0xffffffffu, s2, m);
    }
    if ((tid & 31) == 0) { r1[tid >> 5] = s1; r2[tid >> 5] = s2; }
    __syncthreads();
    float t1 = 0.f, t2 = 0.f;
    #pragma unroll
    for (int i = 0; i < 8; ++i) { t1 += r1[i]; t2 += r2[i]; }
    const float mean = t1 * (1.0f / D);
    const float var  = t2 * (1.0f / D) - mean * mean;
    const float rs   = rsqrtf(var + 1e-5f);
    xn[tid] = (v - mean) * rs * gv[tid] + bv[tid];
    __syncthreads();

    if (tid < H) {
        float a0 = 0.f, a1 = 0.f, a2 = 0.f, a3 = 0.f;
        #pragma unroll 4
        for (int d = 0; d < D; d += 4) {
            a0 = fmaf(xn[d + 0], W[(d + 0) * H + tid], a0);
            a1 = fmaf(xn[d + 1], W[(d + 1) * H + tid], a1);
            a2 = fmaf(xn[d + 2], W[(d + 2) * H + tid], a2);
            a3 = fmaf(xn[d + 3], W[(d + 3) * H + tid], a3);
        }
        float p = (a0 + a1) + (a2 + a3) + bias[tid];
        pr[tid] = p;
        if (is_src) g_src[row * H + tid] = p;
        else        g_th[row * H + tid]  = __float2half(p);
    }
    __syncthreads();

    if (tid < H) {
        const float* Wr = W1 + (is_src ? 0 : H * H);
        float a0 = 0.f, a1 = 0.f, a2 = 0.f, a3 = 0.f;
        #pragma unroll 4
        for (int h = 0; h < H; h += 4) {
            a0 = fmaf(pr[h + 0], Wr[(h + 0) * H + tid], a0);
            a1 = fmaf(pr[h + 1], Wr[(h + 1) * H + tid], a1);
            a2 = fmaf(pr[h + 2], Wr[(h + 2) * H + tid], a2);
            a3 = fmaf(pr[h + 3], Wr[(h + 3) * H + tid], a3);
        }
        float p = (a0 + a1) + (a2 + a3) + (is_src ? b1[tid] : 0.0f);
        (is_src ? g_A : g_C)[row * H + tid] = p;
    }
}

// ---------------------------------------------------------------------------
// Stage 2: mma.sync fp16 fused kernel, cp.async pipelined.
// grid 2048: CTA = (b, s, t-half). 256 threads / 8 warps, 2 CTAs/SM.
// Warp tile: 32t x 32k; CTA iteration tile: 64t x 128k; 4 iterations.
// ---------------------------------------------------------------------------
__device__ __forceinline__ void ldsm_x4(unsigned a, unsigned &r0, unsigned &r1,
                                        unsigned &r2, unsigned &r3) {
    asm volatile("ldmatrix.sync.aligned.m8n8.x4.shared.b16 {%0,%1,%2,%3}, [%4];"
        : "=r"(r0), "=r"(r1), "=r"(r2), "=r"(r3) : "r"(a));
}
__device__ __forceinline__ void ldsm_x4_t(unsigned a, unsigned &r0, unsigned &r1,
                                          unsigned &r2, unsigned &r3) {
    asm volatile("ldmatrix.sync.aligned.m8n8.x4.trans.shared.b16 {%0,%1,%2,%3}, [%4];"
        : "=r"(r0), "=r"(r1), "=r"(r2), "=r"(r3) : "r"(a));
}
__device__ __forceinline__ void mma16816(float* c, const unsigned* a,
                                         unsigned b0, unsigned b1) {
    asm volatile("mma.sync.aligned.m16n8k16.row.col.f32.f16.f16.f32 "
        "{%0,%1,%2,%3}, {%4,%5,%6,%7}, {%8,%9}, {%0,%1,%2,%3};"
        : "+f"(c[0]), "+f"(c[1]), "+f"(c[2]), "+f"(c[3])
        : "r"(a[0]), "r"(a[1]), "r"(a[2]), "r"(a[3]), "r"(b0), "r"(b1));
}
__device__ __forceinline__ void cp16(unsigned dst, const void* src) {
    asm volatile("cp.async.ca.shared.global [%0], [%1], 16;"
        :: "r"(dst), "l"(src) : "memory");
}
__device__ __forceinline__ void cp8(unsigned dst, const void* src) {
    asm volatile("cp.async.ca.shared.global [%0], [%1], 8;"
        :: "r"(dst), "l"(src) : "memory");
}
__device__ __forceinline__ void cp_commit() {
    asm volatile("cp.async.commit_group;" ::: "memory");
}
__device__ __forceinline__ void cp_wait0() {
    asm volatile("cp.async.wait_group 0;" ::: "memory");
}
__device__ __forceinline__ void cp_wait1() {
    asm volatile("cp.async.wait_group 1;" ::: "memory");
}

// smem byte offsets
#define TROWS 64
#define OFF_WHI 0                          // 128*136*2 = 34816
#define OFF_TH0 34816                      // 64*136*2  = 17408
#define OFF_TH1 52224                      // 17408
#define OFF_CB  69632                      // 64*128*4  = 32768 (per-thread slots)
#define OFF_SRC 102400                     // 128 f
#define OFF_AS  (OFF_SRC + 512)
#define OFF_W2  (OFF_AS  + 512)
#define OFF_PS  (OFF_W2  + 512)            // 64*4 f
#define SMEM_BYTES (OFF_PS + 1024)

#define NTHR 256

extern __shared__ char smem_raw[];

__global__ __launch_bounds__(NTHR, 2) void edge_main_kernel(
    const float* __restrict__ W1, const float* __restrict__ W2,
    const float* __restrict__ b2p, const int* __restrict__ mask,
    float* __restrict__ out)
{
    __half* Whi = (__half*)(smem_raw + OFF_WHI);
    float* ssrc = (float*)(smem_raw + OFF_SRC);
    float* As   = (float*)(smem_raw + OFF_AS);
    float* w2s  = (float*)(smem_raw + OFF_W2);
    float* psum = (float*)(smem_raw + OFF_PS);     // [64][4]

    unsigned smem_u32;
    asm("{ .reg .u64 t; cvta.to.shared.u64 t, %1; cvt.u32.u64 %0, t; }"
        : "=r"(smem_u32) : "l"(smem_raw));

    const int bs    = blockIdx.x >> 1;       // 0..1023
    const int thalf = blockIdx.x & 1;        // 0 or 1 (t offset 0 / 256)
    const int b     = bs >> 9;
    const int tid   = threadIdx.x;
    const int wid   = tid >> 5;
    const int lane  = tid & 31;

    // Warp tiling within 64t x 128k iteration tile: 2 t-groups x 4 k-groups
    const int tw0 = (wid >> 2) * 32;    // 0 or 32
    const int kq  = (wid & 3) * 32;     // k base
    const int rL = lane & 15;
    const int cL = (lane >> 4) << 3;

    const int gtbase = (b << 9) + thalf * 256;

    // --- Prefetch C(0): per-thread 16 x 8B into own slot (no barrier needed)
    {
        const unsigned cdst = smem_u32 + OFF_CB + tid * 128;
        int idx = 0;
        #pragma unroll
        for (int f = 0; f < 2; ++f)
            #pragma unroll
            for (int hf = 0; hf < 2; ++hf) {
                const int t = tw0 + f * 16 + (lane >> 2) + hf * 8;
                #pragma unroll
                for (int g = 0; g < 4; ++g) {
                    const int k = kq + g * 8 + (lane & 3) * 2;
                    cp8(cdst + idx * 8, g_C + (gtbase + t) * H + k);
                    ++idx;
                }
            }
        cp_commit();
    }
    // --- Prefetch Th(0) into buf0
    {
        const uint4* sth = (const uint4*)(g_th + gtbase * H);
        #pragma unroll
        for (int i = tid; i < TROWS * 16; i += NTHR) {
            const int row = i >> 4;
            const int c8  = i & 15;
            cp16(smem_u32 + OFF_TH0 + (row * PAD + c8 * 8) * 2, sth + i);
        }
        cp_commit();
    }

    if (tid < H) {
        ssrc[tid] = g_src[bs * H + tid];
        As[tid]   = g_A[bs * H + tid];
        w2s[tid]  = W2[tid];
    }
    __syncthreads();

    // Prologue: Whi[h][k] = fp16( src[h] * W1_st[h][k] )
    {
        const float4* Wst4 = (const float4*)(W1 + 2 * H * H);
        for (int i = tid; i < (H * H) / 4; i += NTHR) {
            const int h = i >> 5;
            const int c = (i & 31) * 4;
            const float sc = ssrc[h];
            float4 w = Wst4[i];
            Whi[h * PAD + c + 0] = __float2half(w.x * sc);
            Whi[h * PAD + c + 1] = __float2half(w.y * sc);
            Whi[h * PAD + c + 2] = __float2half(w.z * sc);
            Whi[h * PAD + c + 3] = __float2half(w.w * sc);
        }
    }

    const float b2v  = b2p[0];
    const float mval = mask[bs] ? 1.0f : 0.0f;

    #pragma unroll 1
    for (int tt = 0; tt < 4; ++tt) {
        const int gt0 = gtbase + tt * TROWS;
        const unsigned thb = smem_u32 + ((tt & 1) ? OFF_TH1 : OFF_TH0);

        // Th(tt) must be complete (group order: Th(tt) older than C(tt))
        if (tt == 0) cp_wait0(); else cp_wait1();
        __syncthreads();

        // Prefetch Th(tt+1) into the other buffer
        if (tt < 3) {
            const unsigned thn = smem_u32 + ((tt & 1) ? OFF_TH0 : OFF_TH1);
            const uint4* sth = (const uint4*)(g_th + (gt0 + TROWS) * H);
            #pragma unroll
            for (int i = tid; i < TROWS * 16; i += NTHR) {
                const int row = i >> 4;
                const int c8  = i & 15;
                cp16(thn + (row * PAD + c8 * 8) * 2, sth + i);
            }
            cp_commit();
        }

        // Mainloop: 32t x 32k per warp, K=128 in 8 steps, single fp16 pass
        float acc[2][4][4];
        #pragma unroll
        for (int f = 0; f < 2; ++f)
            #pragma unroll
            for (int g = 0; g < 4; ++g)
                #pragma unroll
                for (int j = 0; j < 4; ++j) acc[f][g][j] = 0.f;

        #pragma unroll
        for (int step = 0; step < 8; ++step) {
            const int h0 = step * 16;
            unsigned ath[2][4];
            #pragma unroll
            for (int f = 0; f < 2; ++f) {
                unsigned addr = thb + ((tw0 + f * 16 + rL) * PAD + h0 + cL) * 2;
                ldsm_x4(addr, ath[f][0], ath[f][1], ath[f][2], ath[f][3]);
            }
            #pragma unroll
            for (int g = 0; g < 2; ++g) {
                const int nA = kq + g * 16;
                unsigned bh0, bh1, bh2, bh3;
                unsigned baddr = smem_u32 + OFF_WHI + ((h0 + rL) * PAD + nA + cL) * 2;
                ldsm_x4_t(baddr, bh0, bh1, bh2, bh3);
                #pragma unroll
                for (int f = 0; f < 2; ++f) {
                    mma16816(acc[f][2 * g],     ath[f], bh0, bh1);
                    mma16816(acc[f][2 * g + 1], ath[f], bh2, bh3);
                }
            }
        }

        // C(tt) must be complete (only Th(tt+1) may remain pending)
        if (tt == 3) cp_wait0(); else cp_wait1();

        // Epilogue: + A + C, exact gelu, dot W2 over this warp's 32 k,
        // quad-reduce, psum combine, softsign, store.
        const unsigned cslot = smem_u32 + OFF_CB + tid * 128;
        int idx = 0;
        #pragma unroll
        for (int f = 0; f < 2; ++f) {
            #pragma unroll
            for (int hf = 0; hf < 2; ++hf) {
                const int t = tw0 + f * 16 + (lane >> 2) + hf * 8;
                float pt = 0.f;
                #pragma unroll
                for (int g = 0; g < 4; ++g) {
                    const int k = kq + g * 8 + (lane & 3) * 2;
                    float2 cc = *(const float2*)(smem_raw + OFF_CB + tid * 128 + idx * 8);
                    ++idx;
                    float h0v = acc[f][g][hf * 2 + 0] + As[k]     + cc.x;
                    float h1v = acc[f][g][hf * 2 + 1] + As[k + 1] + cc.y;
                    float g0 = 0.5f * h0v * (1.0f + erff(h0v * 0.7071067811865476f));
                    float g1 = 0.5f * h1v * (1.0f + erff(h1v * 0.7071067811865476f));
                    pt = fmaf(g0, w2s[k], pt);
                    pt = fmaf(g1, w2s[k + 1], pt);
                }
                pt += __shfl_xor_sync(0xffffffffu, pt, 1);
                pt += __shfl_xor_sync(0xffffffffu, pt, 2);
                if ((lane & 3) == 0)
                    psum[t * 4 + (wid & 3)] = pt;
            }
        }
        (void)cslot;

        // Prefetch C(tt+1): safe, each thread reuses only its own slot
        if (tt < 3) {
            const unsigned cdst = smem_u32 + OFF_CB + tid * 128;
            int id2 = 0;
            #pragma unroll
            for (int f = 0; f < 2; ++f)
                #pragma unroll
                for (int hf = 0; hf < 2; ++hf) {
                    const int t = tw0 + f * 16 + (lane >> 2) + hf * 8;
                    #pragma unroll
                    for (int g = 0; g < 4; ++g) {
                        const int k = kq + g * 8 + (lane & 3) * 2;
                        cp8(cdst + id2 * 8, g_C + (gt0 + TROWS + t) * H + k);
                        ++id2;
                    }
                }
            cp_commit();
        }

        __syncthreads();
        if (tid < TROWS) {
            const float sc = psum[tid * 4] + psum[tid * 4 + 1]
                           + psum[tid * 4 + 2] + psum[tid * 4 + 3] + b2v;
            const float e  = sc / (1.0f + fabsf(sc));
            out[bs * T + thalf * 256 + tt * TROWS + tid] = e * mval;
        }
    }
}

// ---------------------------------------------------------------------------
extern "C" void kernel_launch(void* const* d_in, const int* in_sizes, int n_in,
                              void* d_out, int out_size)
{
    const float* sv   = (const float*)d_in[0];
    const float* tv   = (const float*)d_in[1];
    const int*   mask = (const int*)d_in[2];
    const float* sng  = (const float*)d_in[3];
    const float* snb  = (const float*)d_in[4];
    const float* tng  = (const float*)d_in[5];
    const float* tnb  = (const float*)d_in[6];
    const float* Wsu  = (const float*)d_in[7];
    const float* bsu  = (const float*)d_in[8];
    const float* Wtp  = (const float*)d_in[9];
    const float* btp  = (const float*)d_in[10];
    const float* W1   = (const float*)d_in[11];
    const float* b1   = (const float*)d_in[12];
    const float* W2   = (const float*)d_in[13];
    const float* b2   = (const float*)d_in[14];
    float* out = (float*)d_out;

    norm_proj_kernel<<<BS + BT, 256>>>(sv, tv, sng, snb, tng, tnb,
                                       Wsu, bsu, Wtp, btp, W1, b1);

    cudaFuncSetAttribute(edge_main_kernel,
                         cudaFuncAttributeMaxDynamicSharedMemorySize, SMEM_BYTES);
    edge_main_kernel<<<2 * BS, NTHR, SMEM_BYTES>>>(W1, W2, b2, mask, out);
}

// round 11
// speedup vs baseline: 2.7093x; 2.7093x over previous
#include <cuda_runtime.h>
#include <cuda_fp16.h>
#include <cstdint>

// Shapes (fixed per reference setup_inputs)
#define B 2
#define S 512
#define T 512
#define D 256
#define H 128
#define BS (B*S)        // 1024
#define BT (B*T)        // 1024

#define PAD 136         // padded row stride (elems) for conflict-free ldmatrix

// Scratch (device globals; no allocation allowed)
__device__ float g_src[BS * H];       // LN(source) @ W_su + b_su (fp32)
__device__ float g_A  [BS * H];       // g_src @ W1_s + b1
__device__ float g_C  [BT * H];       // g_tgt @ W1_t
__device__ __half g_th [BT * H];      // fp16 target proj

// ---------------------------------------------------------------------------
// Stage 1: per-row layernorm + projection + W1_s / W1_t projection.
// ---------------------------------------------------------------------------
__global__ __launch_bounds__(256) void norm_proj_kernel(
    const float* __restrict__ sv, const float* __restrict__ tv,
    const float* __restrict__ sng, const float* __restrict__ snb,
    const float* __restrict__ tng, const float* __restrict__ tnb,
    const float* __restrict__ Wsu, const float* __restrict__ bsu,
    const float* __restrict__ Wtp, const float* __restrict__ btp,
    const float* __restrict__ W1,  const float* __restrict__ b1)
{
    __shared__ float xn[D];
    __shared__ float pr[H];
    __shared__ float r1[8], r2[8];

    const int r = blockIdx.x;
    const bool is_src = (r < BS);
    const int row = is_src ? r : r - BS;
    const int tid = threadIdx.x;

    const float* x    = (is_src ? sv : tv) + row * D;
    const float* gv   = is_src ? sng : tng;
    const float* bv   = is_src ? snb : tnb;
    const float* W    = is_src ? Wsu : Wtp;
    const float* bias = is_src ? bsu : btp;

    float v = x[tid];
    float s1 = v, s2 = v * v;
    #pragma unroll
    for (int m = 16; m; m >>= 1) {
        s1 += __shfl_xor_sync(0xffffffffu, s1, m);
        s2 += __shfl_xor_sync(0xffffffffu, s2, m);
    }
    if ((tid & 31) == 0) { r1[tid >> 5] = s1; r2[tid >> 5] = s2; }
    __syncthreads();
    float t1 = 0.f, t2 = 0.f;
    #pragma unroll
    for (int i = 0; i < 8; ++i) { t1 += r1[i]; t2 += r2[i]; }
    const float mean = t1 * (1.0f / D);
    const float var  = t2 * (1.0f / D) - mean * mean;
    const float rs   = rsqrtf(var + 1e-5f);
    xn[tid] = (v - mean) * rs * gv[tid] + bv[tid];
    __syncthreads();

    if (tid < H) {
        float a0 = 0.f, a1 = 0.f, a2 = 0.f, a3 = 0.f;
        #pragma unroll 4
        for (int d = 0; d < D; d += 4) {
            a0 = fmaf(xn[d + 0], W[(d + 0) * H + tid], a0);
            a1 = fmaf(xn[d + 1], W[(d + 1) * H + tid], a1);
            a2 = fmaf(xn[d + 2], W[(d + 2) * H + tid], a2);
            a3 = fmaf(xn[d + 3], W[(d + 3) * H + tid], a3);
        }
        float p = (a0 + a1) + (a2 + a3) + bias[tid];
        pr[tid] = p;
        if (is_src) g_src[row * H + tid] = p;
        else        g_th[row * H + tid]  = __float2half(p);
    }
    __syncthreads();

    if (tid < H) {
        const float* Wr = W1 + (is_src ? 0 : H * H);
        float a0 = 0.f, a1 = 0.f, a2 = 0.f, a3 = 0.f;
        #pragma unroll 4
        for (int h = 0; h < H; h += 4) {
            a0 = fmaf(pr[h + 0], Wr[(h + 0) * H + tid], a0);
            a1 = fmaf(pr[h + 1], Wr[(h + 1) * H + tid], a1);
            a2 = fmaf(pr[h + 2], Wr[(h + 2) * H + tid], a2);
            a3 = fmaf(pr[h + 3], Wr[(h + 3) * H + tid], a3);
        }
        float p = (a0 + a1) + (a2 + a3) + (is_src ? b1[tid] : 0.0f);
        (is_src ? g_A : g_C)[row * H + tid] = p;
    }
}

// ---------------------------------------------------------------------------
// Stage 2: mma.sync fp16 fused kernel, Th double-buffered via cp.async.
// grid 2048: CTA = (b, s, t-half). 256 threads / 8 warps, 2 CTAs/SM.
// Warp tile: 32t x 32k; CTA iteration tile: 64t x 128k; 4 iterations.
// ---------------------------------------------------------------------------
__device__ __forceinline__ void ldsm_x4(unsigned a, unsigned &r0, unsigned &r1,
                                        unsigned &r2, unsigned &r3) {
    asm volatile("ldmatrix.sync.aligned.m8n8.x4.shared.b16 {%0,%1,%2,%3}, [%4];"
        : "=r"(r0), "=r"(r1), "=r"(r2), "=r"(r3) : "r"(a));
}
__device__ __forceinline__ void ldsm_x4_t(unsigned a, unsigned &r0, unsigned &r1,
                                          unsigned &r2, unsigned &r3) {
    asm volatile("ldmatrix.sync.aligned.m8n8.x4.trans.shared.b16 {%0,%1,%2,%3}, [%4];"
        : "=r"(r0), "=r"(r1), "=r"(r2), "=r"(r3) : "r"(a));
}
__device__ __forceinline__ void mma16816(float* c, const unsigned* a,
                                         unsigned b0, unsigned b1) {
    asm volatile("mma.sync.aligned.m16n8k16.row.col.f32.f16.f16.f32 "
        "{%0,%1,%2,%3}, {%4,%5,%6,%7}, {%8,%9}, {%0,%1,%2,%3};"
        : "+f"(c[0]), "+f"(c[1]), "+f"(c[2]), "+f"(c[3])
        : "r"(a[0]), "r"(a[1]), "r"(a[2]), "r"(a[3]), "r"(b0), "r"(b1));
}
__device__ __forceinline__ void cp16(unsigned dst, const void* src) {
    asm volatile("cp.async.ca.shared.global [%0], [%1], 16;"
        :: "r"(dst), "l"(src) : "memory");
}
__device__ __forceinline__ void cp_commit() {
    asm volatile("cp.async.commit_group;" ::: "memory");
}
__device__ __forceinline__ void cp_wait0() {
    asm volatile("cp.async.wait_group 0;" ::: "memory");
}

// smem byte offsets
#define TROWS 64
#define OFF_WHI 0                          // 128*136*2 = 34816
#define OFF_TH0 34816                      // 64*136*2  = 17408
#define OFF_TH1 52224                      // 17408
#define OFF_SRC 69632                      // 128 f
#define OFF_AS  (OFF_SRC + 512)
#define OFF_W2  (OFF_AS  + 512)
#define OFF_PS  (OFF_W2  + 512)            // 64*4 f
#define SMEM_BYTES (OFF_PS + 1024)

#define NTHR 256

extern __shared__ char smem_raw[];

__global__ __launch_bounds__(NTHR, 2) void edge_main_kernel(
    const float* __restrict__ W1, const float* __restrict__ W2,
    const float* __restrict__ b2p, const int* __restrict__ mask,
    float* __restrict__ out)
{
    __half* Whi = (__half*)(smem_raw + OFF_WHI);
    float* ssrc = (float*)(smem_raw + OFF_SRC);
    float* As   = (float*)(smem_raw + OFF_AS);
    float* w2s  = (float*)(smem_raw + OFF_W2);
    float* psum = (float*)(smem_raw + OFF_PS);     // [64][4]

    unsigned smem_u32;
    asm("{ .reg .u64 t; cvta.to.shared.u64 t, %1; cvt.u32.u64 %0, t; }"
        : "=r"(smem_u32) : "l"(smem_raw));

    const int bs    = blockIdx.x >> 1;       // 0..1023
    const int thalf = blockIdx.x & 1;        // 0 or 1 (t offset 0 / 256)
    const int b     = bs >> 9;
    const int tid   = threadIdx.x;
    const int wid   = tid >> 5;
    const int lane  = tid & 31;

    // Warp tiling within 64t x 128k iteration tile: 2 t-groups x 4 k-groups
    const int tw0 = (wid >> 2) * 32;    // 0 or 32
    const int kq  = (wid & 3) * 32;     // k base
    const int rL = lane & 15;
    const int cL = (lane >> 4) << 3;

    const int gtbase = (b << 9) + thalf * 256;

    // Prefetch Th(0) into buf0 (coalesced 16B cp.async) — overlaps prologue
    {
        const uint4* sth = (const uint4*)(g_th + gtbase * H);
        #pragma unroll
        for (int i = tid; i < TROWS * 16; i += NTHR) {
            const int row = i >> 4;
            const int c8  = i & 15;
            cp16(smem_u32 + OFF_TH0 + (row * PAD + c8 * 8) * 2, sth + i);
        }
        cp_commit();
    }

    if (tid < H) {
        ssrc[tid] = g_src[bs * H + tid];
        As[tid]   = g_A[bs * H + tid];
        w2s[tid]  = W2[tid];
    }
    __syncthreads();

    // Prologue: Whi[h][k] = fp16( src[h] * W1_st[h][k] )
    {
        const float4* Wst4 = (const float4*)(W1 + 2 * H * H);
        for (int i = tid; i < (H * H) / 4; i += NTHR) {
            const int h = i >> 5;
            const int c = (i & 31) * 4;
            const float sc = ssrc[h];
            float4 w = Wst4[i];
            Whi[h * PAD + c + 0] = __float2half(w.x * sc);
            Whi[h * PAD + c + 1] = __float2half(w.y * sc);
            Whi[h * PAD + c + 2] = __float2half(w.z * sc);
            Whi[h * PAD + c + 3] = __float2half(w.w * sc);
        }
    }

    const float b2v  = b2p[0];
    const float mval = mask[bs] ? 1.0f : 0.0f;

    #pragma unroll 1
    for (int tt = 0; tt < 4; ++tt) {
        const int gt0 = gtbase + tt * TROWS;
        const unsigned thb = smem_u32 + ((tt & 1) ? OFF_TH1 : OFF_TH0);

        cp_wait0();          // Th(tt) copies issued by this thread done
        __syncthreads();     // all threads' copies visible

        // Prefetch Th(tt+1) into the other buffer (disjoint from thb)
        if (tt < 3) {
            const unsigned thn = smem_u32 + ((tt & 1) ? OFF_TH0 : OFF_TH1);
            const uint4* sth = (const uint4*)(g_th + (gt0 + TROWS) * H);
            #pragma unroll
            for (int i = tid; i < TROWS * 16; i += NTHR) {
                const int row = i >> 4;
                const int c8  = i & 15;
                cp16(thn + (row * PAD + c8 * 8) * 2, sth + i);
            }
            cp_commit();
        }

        // Mainloop: 32t x 32k per warp, K=128 in 8 steps, single fp16 pass
        float acc[2][4][4];
        #pragma unroll
        for (int f = 0; f < 2; ++f)
            #pragma unroll
            for (int g = 0; g < 4; ++g)
                #pragma unroll
                for (int j = 0; j < 4; ++j) acc[f][g][j] = 0.f;

        #pragma unroll
        for (int step = 0; step < 8; ++step) {
            const int h0 = step * 16;
            unsigned ath[2][4];
            #pragma unroll
            for (int f = 0; f < 2; ++f) {
                unsigned addr = thb + ((tw0 + f * 16 + rL) * PAD + h0 + cL) * 2;
                ldsm_x4(addr, ath[f][0], ath[f][1], ath[f][2], ath[f][3]);
            }
            #pragma unroll
            for (int g = 0; g < 2; ++g) {
                const int nA = kq + g * 16;
                unsigned bh0, bh1, bh2, bh3;
                unsigned baddr = smem_u32 + OFF_WHI + ((h0 + rL) * PAD + nA + cL) * 2;
                ldsm_x4_t(baddr, bh0, bh1, bh2, bh3);
                #pragma unroll
                for (int f = 0; f < 2; ++f) {
                    mma16816(acc[f][2 * g],     ath[f], bh0, bh1);
                    mma16816(acc[f][2 * g + 1], ath[f], bh2, bh3);
                }
            }
        }

        // Epilogue: + A + C (plain LDG), exact gelu, dot W2, quad-reduce,
        // psum combine, softsign, store.
        #pragma unroll
        for (int f = 0; f < 2; ++f) {
            #pragma unroll
            for (int hf = 0; hf < 2; ++hf) {
                const int t = tw0 + f * 16 + (lane >> 2) + hf * 8;
                const float2* Cr = (const float2*)(g_C + (gt0 + t) * H);
                float pt = 0.f;
                #pragma unroll
                for (int g = 0; g < 4; ++g) {
                    const int k = kq + g * 8 + (lane & 3) * 2;
                    const float2 cc = Cr[k >> 1];
                    float h0v = acc[f][g][hf * 2 + 0] + As[k]     + cc.x;
                    float h1v = acc[f][g][hf * 2 + 1] + As[k + 1] + cc.y;
                    float g0 = 0.5f * h0v * (1.0f + erff(h0v * 0.7071067811865476f));
                    float g1 = 0.5f * h1v * (1.0f + erff(h1v * 0.7071067811865476f));
                    pt = fmaf(g0, w2s[k], pt);
                    pt = fmaf(g1, w2s[k + 1], pt);
                }
                pt += __shfl_xor_sync(0xffffffffu, pt, 1);
                pt += __shfl_xor_sync(0xffffffffu, pt, 2);
                if ((lane & 3) == 0)
                    psum[t * 4 + (wid & 3)] = pt;
            }
        }
        __syncthreads();

        if (tid < TROWS) {
            const float sc = psum[tid * 4] + psum[tid * 4 + 1]
                           + psum[tid * 4 + 2] + psum[tid * 4 + 3] + b2v;
            const float e  = sc / (1.0f + fabsf(sc));
            out[bs * T + thalf * 256 + tt * TROWS + tid] = e * mval;
        }
    }
}

// ---------------------------------------------------------------------------
extern "C" void kernel_launch(void* const* d_in, const int* in_sizes, int n_in,
                              void* d_out, int out_size)
{
    const float* sv   = (const float*)d_in[0];
    const float* tv   = (const float*)d_in[1];
    const int*   mask = (const int*)d_in[2];
    const float* sng  = (const float*)d_in[3];
    const float* snb  = (const float*)d_in[4];
    const float* tng  = (const float*)d_in[5];
    const float* tnb  = (const float*)d_in[6];
    const float* Wsu  = (const float*)d_in[7];
    const float* bsu  = (const float*)d_in[8];
    const float* Wtp  = (const float*)d_in[9];
    const float* btp  = (const float*)d_in[10];
    const float* W1   = (const float*)d_in[11];
    const float* b1   = (const float*)d_in[12];
    const float* W2   = (const float*)d_in[13];
    const float* b2   = (const float*)d_in[14];
    float* out = (float*)d_out;

    norm_proj_kernel<<<BS + BT, 256>>>(sv, tv, sng, snb, tng, tnb,
                                       Wsu, bsu, Wtp, btp, W1, b1);

    cudaFuncSetAttribute(edge_main_kernel,
                         cudaFuncAttributeMaxDynamicSharedMemorySize, SMEM_BYTES);
    edge_main_kernel<<<2 * BS, NTHR, SMEM_BYTES>>>(W1, W2, b2, mask, out);
}

// round 12
// speedup vs baseline: 2.9435x; 1.0864x over previous
#include <cuda_runtime.h>
#include <cuda_fp16.h>
#include <cstdint>

// Shapes (fixed per reference setup_inputs)
#define B 2
#define S 512
#define T 512
#define D 256
#define H 128
#define BS (B*S)        // 1024
#define BT (B*T)        // 1024

#define PAD 136         // padded row stride (elems) for conflict-free ldmatrix

// Scratch (device globals; no allocation allowed)
__device__ float g_src[BS * H];       // LN(source) @ W_su + b_su (fp32)
__device__ float g_A  [BS * H];       // g_src @ W1_s + b1
__device__ __half g_th [BT * H];      // fp16 target proj

// ---------------------------------------------------------------------------
// Stage 1: per-row layernorm + projection (+ W1_s projection for source).
// ---------------------------------------------------------------------------
__global__ __launch_bounds__(256) void norm_proj_kernel(
    const float* __restrict__ sv, const float* __restrict__ tv,
    const float* __restrict__ sng, const float* __restrict__ snb,
    const float* __restrict__ tng, const float* __restrict__ tnb,
    const float* __restrict__ Wsu, const float* __restrict__ bsu,
    const float* __restrict__ Wtp, const float* __restrict__ btp,
    const float* __restrict__ W1,  const float* __restrict__ b1)
{
    __shared__ float xn[D];
    __shared__ float pr[H];
    __shared__ float r1[8], r2[8];

    const int r = blockIdx.x;
    const bool is_src = (r < BS);
    const int row = is_src ? r : r - BS;
    const int tid = threadIdx.x;

    const float* x    = (is_src ? sv : tv) + row * D;
    const float* gv   = is_src ? sng : tng;
    const float* bv   = is_src ? snb : tnb;
    const float* W    = is_src ? Wsu : Wtp;
    const float* bias = is_src ? bsu : btp;

    float v = x[tid];
    float s1 = v, s2 = v * v;
    #pragma unroll
    for (int m = 16; m; m >>= 1) {
        s1 += __shfl_xor_sync(0xffffffffu, s1, m);
        s2 += __shfl_xor_sync(0xffffffffu, s2, m);
    }
    if ((tid & 31) == 0) { r1[tid >> 5] = s1; r2[tid >> 5] = s2; }
    __syncthreads();
    float t1 = 0.f, t2 = 0.f;
    #pragma unroll
    for (int i = 0; i < 8; ++i) { t1 += r1[i]; t2 += r2[i]; }
    const float mean = t1 * (1.0f / D);
    const float var  = t2 * (1.0f / D) - mean * mean;
    const float rs   = rsqrtf(var + 1e-5f);
    xn[tid] = (v - mean) * rs * gv[tid] + bv[tid];
    __syncthreads();

    if (tid < H) {
        float a0 = 0.f, a1 = 0.f, a2 = 0.f, a3 = 0.f;
        #pragma unroll 4
        for (int d = 0; d < D; d += 4) {
            a0 = fmaf(xn[d + 0], W[(d + 0) * H + tid], a0);
            a1 = fmaf(xn[d + 1], W[(d + 1) * H + tid], a1);
            a2 = fmaf(xn[d + 2], W[(d + 2) * H + tid], a2);
            a3 = fmaf(xn[d + 3], W[(d + 3) * H + tid], a3);
        }
        float p = (a0 + a1) + (a2 + a3) + bias[tid];
        pr[tid] = p;
        if (is_src) g_src[row * H + tid] = p;
        else        g_th[row * H + tid]  = __float2half(p);
    }
    __syncthreads();

    // Only source rows need A = proj @ W1_s + b1 (C-term folded into stage 2)
    if (is_src && tid < H) {
        const float* Wr = W1;
        float a0 = 0.f, a1 = 0.f, a2 = 0.f, a3 = 0.f;
        #pragma unroll 4
        for (int h = 0; h < H; h += 4) {
            a0 = fmaf(pr[h + 0], Wr[(h + 0) * H + tid], a0);
            a1 = fmaf(pr[h + 1], Wr[(h + 1) * H + tid], a1);
            a2 = fmaf(pr[h + 2], Wr[(h + 2) * H + tid], a2);
            a3 = fmaf(pr[h + 3], Wr[(h + 3) * H + tid], a3);
        }
        g_A[row * H + tid] = (a0 + a1) + (a2 + a3) + b1[tid];
    }
}

// ---------------------------------------------------------------------------
// Stage 2: mma.sync fp16 fused kernel, C-term folded into the weight.
// W_tot[h][k] = src[h]*W1_st[h][k] + W1_t[h][k]  (fp16)
// hidden[t,k] = tgt[t]·W_tot[:,k] + A[s,k]
// grid 2048: CTA = (b, s, t-half). 256 threads / 8 warps, 2 CTAs/SM.
// ---------------------------------------------------------------------------
__device__ __forceinline__ void ldsm_x4(unsigned a, unsigned &r0, unsigned &r1,
                                        unsigned &r2, unsigned &r3) {
    asm volatile("ldmatrix.sync.aligned.m8n8.x4.shared.b16 {%0,%1,%2,%3}, [%4];"
        : "=r"(r0), "=r"(r1), "=r"(r2), "=r"(r3) : "r"(a));
}
__device__ __forceinline__ void ldsm_x4_t(unsigned a, unsigned &r0, unsigned &r1,
                                          unsigned &r2, unsigned &r3) {
    asm volatile("ldmatrix.sync.aligned.m8n8.x4.trans.shared.b16 {%0,%1,%2,%3}, [%4];"
        : "=r"(r0), "=r"(r1), "=r"(r2), "=r"(r3) : "r"(a));
}
__device__ __forceinline__ void mma16816(float* c, const unsigned* a,
                                         unsigned b0, unsigned b1) {
    asm volatile("mma.sync.aligned.m16n8k16.row.col.f32.f16.f16.f32 "
        "{%0,%1,%2,%3}, {%4,%5,%6,%7}, {%8,%9}, {%0,%1,%2,%3};"
        : "+f"(c[0]), "+f"(c[1]), "+f"(c[2]), "+f"(c[3])
        : "r"(a[0]), "r"(a[1]), "r"(a[2]), "r"(a[3]), "r"(b0), "r"(b1));
}
__device__ __forceinline__ void cp16(unsigned dst, const void* src) {
    asm volatile("cp.async.ca.shared.global [%0], [%1], 16;"
        :: "r"(dst), "l"(src) : "memory");
}
__device__ __forceinline__ void cp_commit() {
    asm volatile("cp.async.commit_group;" ::: "memory");
}
__device__ __forceinline__ void cp_wait0() {
    asm volatile("cp.async.wait_group 0;" ::: "memory");
}

// smem byte offsets
#define TROWS 64
#define OFF_WHI 0                          // 128*136*2 = 34816
#define OFF_TH0 34816                      // 64*136*2  = 17408
#define OFF_TH1 52224                      // 17408
#define OFF_SRC 69632                      // 128 f
#define OFF_AS  (OFF_SRC + 512)
#define OFF_W2  (OFF_AS  + 512)
#define OFF_PS  (OFF_W2  + 512)            // 64*4 f
#define SMEM_BYTES (OFF_PS + 1024)

#define NTHR 256

extern __shared__ char smem_raw[];

__global__ __launch_bounds__(NTHR, 2) void edge_main_kernel(
    const float* __restrict__ W1, const float* __restrict__ W2,
    const float* __restrict__ b2p, const int* __restrict__ mask,
    float* __restrict__ out)
{
    __half* Whi = (__half*)(smem_raw + OFF_WHI);
    float* ssrc = (float*)(smem_raw + OFF_SRC);
    float* As   = (float*)(smem_raw + OFF_AS);
    float* w2s  = (float*)(smem_raw + OFF_W2);
    float* psum = (float*)(smem_raw + OFF_PS);     // [64][4]

    unsigned smem_u32;
    asm("{ .reg .u64 t; cvta.to.shared.u64 t, %1; cvt.u32.u64 %0, t; }"
        : "=r"(smem_u32) : "l"(smem_raw));

    const int bs    = blockIdx.x >> 1;       // 0..1023
    const int thalf = blockIdx.x & 1;        // 0 or 1 (t offset 0 / 256)
    const int b     = bs >> 9;
    const int tid   = threadIdx.x;
    const int wid   = tid >> 5;
    const int lane  = tid & 31;

    // Warp tiling within 64t x 128k iteration tile: 2 t-groups x 4 k-groups
    const int tw0 = (wid >> 2) * 32;    // 0 or 32
    const int kq  = (wid & 3) * 32;     // k base
    const int rL = lane & 15;
    const int cL = (lane >> 4) << 3;

    const int gtbase = (b << 9) + thalf * 256;

    // Prefetch Th(0) into buf0 (coalesced 16B cp.async) — overlaps prologue
    {
        const uint4* sth = (const uint4*)(g_th + gtbase * H);
        #pragma unroll
        for (int i = tid; i < TROWS * 16; i += NTHR) {
            const int row = i >> 4;
            const int c8  = i & 15;
            cp16(smem_u32 + OFF_TH0 + (row * PAD + c8 * 8) * 2, sth + i);
        }
        cp_commit();
    }

    if (tid < H) {
        ssrc[tid] = g_src[bs * H + tid];
        As[tid]   = g_A[bs * H + tid];
        w2s[tid]  = W2[tid];
    }
    __syncthreads();

    // Prologue: Whi[h][k] = fp16( src[h]*W1_st[h][k] + W1_t[h][k] )
    {
        const float4* Wst4 = (const float4*)(W1 + 2 * H * H);
        const float4* Wt4  = (const float4*)(W1 + 1 * H * H);
        for (int i = tid; i < (H * H) / 4; i += NTHR) {
            const int h = i >> 5;
            const int c = (i & 31) * 4;
            const float sc = ssrc[h];
            float4 w = Wst4[i];
            float4 wt = Wt4[i];
            Whi[h * PAD + c + 0] = __float2half(fmaf(w.x, sc, wt.x));
            Whi[h * PAD + c + 1] = __float2half(fmaf(w.y, sc, wt.y));
            Whi[h * PAD + c + 2] = __float2half(fmaf(w.z, sc, wt.z));
            Whi[h * PAD + c + 3] = __float2half(fmaf(w.w, sc, wt.w));
        }
    }
    __syncthreads();   // As/w2s fully written before register caching

    // Register-cache per-thread A and W2 values (iteration-invariant)
    float asr[8], w2r[8];
    #pragma unroll
    for (int g = 0; g < 4; ++g) {
        const int k = kq + g * 8 + (lane & 3) * 2;
        asr[2 * g]     = As[k];
        asr[2 * g + 1] = As[k + 1];
        w2r[2 * g]     = w2s[k];
        w2r[2 * g + 1] = w2s[k + 1];
    }

    const float b2v  = b2p[0];
    const float mval = mask[bs] ? 1.0f : 0.0f;

    #pragma unroll 1
    for (int tt = 0; tt < 4; ++tt) {
        const int gt0 = gtbase + tt * TROWS;
        const unsigned thb = smem_u32 + ((tt & 1) ? OFF_TH1 : OFF_TH0);

        cp_wait0();          // Th(tt) copies issued by this thread done
        __syncthreads();     // all threads' copies visible

        // Prefetch Th(tt+1) into the other buffer (disjoint from thb)
        if (tt < 3) {
            const unsigned thn = smem_u32 + ((tt & 1) ? OFF_TH0 : OFF_TH1);
            const uint4* sth = (const uint4*)(g_th + (gt0 + TROWS) * H);
            #pragma unroll
            for (int i = tid; i < TROWS * 16; i += NTHR) {
                const int row = i >> 4;
                const int c8  = i & 15;
                cp16(thn + (row * PAD + c8 * 8) * 2, sth + i);
            }
            cp_commit();
        }

        // Mainloop: 32t x 32k per warp, K=128 in 8 steps, single fp16 pass
        float acc[2][4][4];
        #pragma unroll
        for (int f = 0; f < 2; ++f)
            #pragma unroll
            for (int g = 0; g < 4; ++g)
                #pragma unroll
                for (int j = 0; j < 4; ++j) acc[f][g][j] = 0.f;

        #pragma unroll
        for (int step = 0; step < 8; ++step) {
            const int h0 = step * 16;
            unsigned ath[2][4];
            #pragma unroll
            for (int f = 0; f < 2; ++f) {
                unsigned addr = thb + ((tw0 + f * 16 + rL) * PAD + h0 + cL) * 2;
                ldsm_x4(addr, ath[f][0], ath[f][1], ath[f][2], ath[f][3]);
            }
            #pragma unroll
            for (int g = 0; g < 2; ++g) {
                const int nA = kq + g * 16;
                unsigned bh0, bh1, bh2, bh3;
                unsigned baddr = smem_u32 + OFF_WHI + ((h0 + rL) * PAD + nA + cL) * 2;
                ldsm_x4_t(baddr, bh0, bh1, bh2, bh3);
                #pragma unroll
                for (int f = 0; f < 2; ++f) {
                    mma16816(acc[f][2 * g],     ath[f], bh0, bh1);
                    mma16816(acc[f][2 * g + 1], ath[f], bh2, bh3);
                }
            }
        }

        // Epilogue: + A, exact gelu, dot W2, quad-reduce, psum combine,
        // softsign, store.  (C-term already inside the GEMM.)
        #pragma unroll
        for (int f = 0; f < 2; ++f) {
            #pragma unroll
            for (int hf = 0; hf < 2; ++hf) {
                const int t = tw0 + f * 16 + (lane >> 2) + hf * 8;
                float pt = 0.f;
                #pragma unroll
                for (int g = 0; g < 4; ++g) {
                    float h0v = acc[f][g][hf * 2 + 0] + asr[2 * g];
                    float h1v = acc[f][g][hf * 2 + 1] + asr[2 * g + 1];
                    float g0 = 0.5f * h0v * (1.0f + erff(h0v * 0.7071067811865476f));
                    float g1 = 0.5f * h1v * (1.0f + erff(h1v * 0.7071067811865476f));
                    pt = fmaf(g0, w2r[2 * g], pt);
                    pt = fmaf(g1, w2r[2 * g + 1], pt);
                }
                pt += __shfl_xor_sync(0xffffffffu, pt, 1);
                pt += __shfl_xor_sync(0xffffffffu, pt, 2);
                if ((lane & 3) == 0)
                    psum[t * 4 + (wid & 3)] = pt;
            }
        }
        __syncthreads();

        if (tid < TROWS) {
            const float sc = psum[tid * 4] + psum[tid * 4 + 1]
                           + psum[tid * 4 + 2] + psum[tid * 4 + 3] + b2v;
            const float e  = sc / (1.0f + fabsf(sc));
            out[bs * T + thalf * 256 + tt * TROWS + tid] = e * mval;
        }
    }
}

// ---------------------------------------------------------------------------
extern "C" void kernel_launch(void* const* d_in, const int* in_sizes, int n_in,
                              void* d_out, int out_size)
{
    const float* sv   = (const float*)d_in[0];
    const float* tv   = (const float*)d_in[1];
    const int*   mask = (const int*)d_in[2];
    const float* sng  = (const float*)d_in[3];
    const float* snb  = (const float*)d_in[4];
    const float* tng  = (const float*)d_in[5];
    const float* tnb  = (const float*)d_in[6];
    const float* Wsu  = (const float*)d_in[7];
    const float* bsu  = (const float*)d_in[8];
    const float* Wtp  = (const float*)d_in[9];
    const float* btp  = (const float*)d_in[10];
    const float* W1   = (const float*)d_in[11];
    const float* b1   = (const float*)d_in[12];
    const float* W2   = (const float*)d_in[13];
    const float* b2   = (const float*)d_in[14];
    float* out = (float*)d_out;

    norm_proj_kernel<<<BS + BT, 256>>>(sv, tv, sng, snb, tng, tnb,
                                       Wsu, bsu, Wtp, btp, W1, b1);

    cudaFuncSetAttribute(edge_main_kernel,
                         cudaFuncAttributeMaxDynamicSharedMemorySize, SMEM_BYTES);
    edge_main_kernel<<<2 * BS, NTHR, SMEM_BYTES>>>(W1, W2, b2, mask, out);
}

// round 13
// speedup vs baseline: 2.9750x; 1.0107x over previous
#include <cuda_runtime.h>
#include <cuda_fp16.h>
#include <cstdint>

// Shapes (fixed per reference setup_inputs)
#define B 2
#define S 512
#define T 512
#define D 256
#define H 128
#define BS (B*S)        // 1024
#define BT (B*T)        // 1024

#define PAD 136         // padded row stride (elems) for conflict-free ldmatrix

// Scratch (device globals; no allocation allowed)
__device__ float g_src[BS * H];       // LN(source) @ W_su + b_su (fp32)
__device__ float g_A  [BS * H];       // g_src @ W1_s + b1
__device__ __half g_th [BT * H];      // fp16 target proj

// ---------------------------------------------------------------------------
// Stage 1: per-row layernorm + projection (+ W1_s projection for source).
// ---------------------------------------------------------------------------
__global__ __launch_bounds__(256) void norm_proj_kernel(
    const float* __restrict__ sv, const float* __restrict__ tv,
    const float* __restrict__ sng, const float* __restrict__ snb,
    const float* __restrict__ tng, const float* __restrict__ tnb,
    const float* __restrict__ Wsu, const float* __restrict__ bsu,
    const float* __restrict__ Wtp, const float* __restrict__ btp,
    const float* __restrict__ W1,  const float* __restrict__ b1)
{
    __shared__ float xn[D];
    __shared__ float pr[H];
    __shared__ float r1[8], r2[8];

    const int r = blockIdx.x;
    const bool is_src = (r < BS);
    const int row = is_src ? r : r - BS;
    const int tid = threadIdx.x;

    const float* x    = (is_src ? sv : tv) + row * D;
    const float* gv   = is_src ? sng : tng;
    const float* bv   = is_src ? snb : tnb;
    const float* W    = is_src ? Wsu : Wtp;
    const float* bias = is_src ? bsu : btp;

    float v = x[tid];
    float s1 = v, s2 = v * v;
    #pragma unroll
    for (int m = 16; m; m >>= 1) {
        s1 += __shfl_xor_sync(0xffffffffu, s1, m);
        s2 += __shfl_xor_sync(0xffffffffu, s2, m);
    }
    if ((tid & 31) == 0) { r1[tid >> 5] = s1; r2[tid >> 5] = s2; }
    __syncthreads();
    float t1 = 0.f, t2 = 0.f;
    #pragma unroll
    for (int i = 0; i < 8; ++i) { t1 += r1[i]; t2 += r2[i]; }
    const float mean = t1 * (1.0f / D);
    const float var  = t2 * (1.0f / D) - mean * mean;
    const float rs   = rsqrtf(var + 1e-5f);
    xn[tid] = (v - mean) * rs * gv[tid] + bv[tid];
    __syncthreads();

    if (tid < H) {
        float a0 = 0.f, a1 = 0.f, a2 = 0.f, a3 = 0.f;
        #pragma unroll 4
        for (int d = 0; d < D; d += 4) {
            a0 = fmaf(xn[d + 0], W[(d + 0) * H + tid], a0);
            a1 = fmaf(xn[d + 1], W[(d + 1) * H + tid], a1);
            a2 = fmaf(xn[d + 2], W[(d + 2) * H + tid], a2);
            a3 = fmaf(xn[d + 3], W[(d + 3) * H + tid], a3);
        }
        float p = (a0 + a1) + (a2 + a3) + bias[tid];
        pr[tid] = p;
        if (is_src) g_src[row * H + tid] = p;
        else        g_th[row * H + tid]  = __float2half(p);
    }
    __syncthreads();

    // Only source rows need A = proj @ W1_s + b1 (C-term folded into stage 2)
    if (is_src && tid < H) {
        const float* Wr = W1;
        float a0 = 0.f, a1 = 0.f, a2 = 0.f, a3 = 0.f;
        #pragma unroll 4
        for (int h = 0; h < H; h += 4) {
            a0 = fmaf(pr[h + 0], Wr[(h + 0) * H + tid], a0);
            a1 = fmaf(pr[h + 1], Wr[(h + 1) * H + tid], a1);
            a2 = fmaf(pr[h + 2], Wr[(h + 2) * H + tid], a2);
            a3 = fmaf(pr[h + 3], Wr[(h + 3) * H + tid], a3);
        }
        g_A[row * H + tid] = (a0 + a1) + (a2 + a3) + b1[tid];
    }
}

// ---------------------------------------------------------------------------
// Fast exact-gelu: Abramowitz-Stegun 7.1.26 erf (|err| <= 1.5e-7), branchless.
// ---------------------------------------------------------------------------
__device__ __forceinline__ float gelu_fast(float x) {
    const float u  = x * 0.7071067811865476f;
    const float au = fabsf(u);
    const float d  = fmaf(0.3275911f, au, 1.0f);
    float t;
    asm("rcp.approx.f32 %0, %1;" : "=f"(t) : "f"(d));
    float e;
    const float y = -au * au * 1.4426950408889634f;   // -u^2 * log2(e)
    asm("ex2.approx.f32 %0, %1;" : "=f"(e) : "f"(y));
    float p = fmaf(1.061405429f, t, -1.453152027f);
    p = fmaf(p, t, 1.421413741f);
    p = fmaf(p, t, -0.284496736f);
    p = fmaf(p, t, 0.254829592f);
    p = p * t;
    float r = fmaf(-p, e, 1.0f);                      // erf(|u|)
    r = copysignf(r, u);                              // erf(u)
    return 0.5f * x * (1.0f + r);
}

// ---------------------------------------------------------------------------
// Stage 2: mma.sync fp16 fused kernel, C-term folded into the weight.
// W_tot[h][k] = src[h]*W1_st[h][k] + W1_t[h][k]  (fp16)
// hidden[t,k] = tgt[t]·W_tot[:,k] + A[s,k]
// grid 2048: CTA = (b, s, t-half). 256 threads / 8 warps, 2 CTAs/SM.
// ---------------------------------------------------------------------------
__device__ __forceinline__ void ldsm_x4(unsigned a, unsigned &r0, unsigned &r1,
                                        unsigned &r2, unsigned &r3) {
    asm volatile("ldmatrix.sync.aligned.m8n8.x4.shared.b16 {%0,%1,%2,%3}, [%4];"
        : "=r"(r0), "=r"(r1), "=r"(r2), "=r"(r3) : "r"(a));
}
__device__ __forceinline__ void ldsm_x4_t(unsigned a, unsigned &r0, unsigned &r1,
                                          unsigned &r2, unsigned &r3) {
    asm volatile("ldmatrix.sync.aligned.m8n8.x4.trans.shared.b16 {%0,%1,%2,%3}, [%4];"
        : "=r"(r0), "=r"(r1), "=r"(r2), "=r"(r3) : "r"(a));
}
__device__ __forceinline__ void mma16816(float* c, const unsigned* a,
                                         unsigned b0, unsigned b1) {
    asm volatile("mma.sync.aligned.m16n8k16.row.col.f32.f16.f16.f32 "
        "{%0,%1,%2,%3}, {%4,%5,%6,%7}, {%8,%9}, {%0,%1,%2,%3};"
        : "+f"(c[0]), "+f"(c[1]), "+f"(c[2]), "+f"(c[3])
        : "r"(a[0]), "r"(a[1]), "r"(a[2]), "r"(a[3]), "r"(b0), "r"(b1));
}
__device__ __forceinline__ void cp16(unsigned dst, const void* src) {
    asm volatile("cp.async.ca.shared.global [%0], [%1], 16;"
        :: "r"(dst), "l"(src) : "memory");
}
__device__ __forceinline__ void cp_commit() {
    asm volatile("cp.async.commit_group;" ::: "memory");
}
__device__ __forceinline__ void cp_wait0() {
    asm volatile("cp.async.wait_group 0;" ::: "memory");
}

// smem byte offsets
#define TROWS 64
#define OFF_WHI 0                          // 128*136*2 = 34816
#define OFF_TH0 34816                      // 64*136*2  = 17408
#define OFF_TH1 52224                      // 17408
#define OFF_SRC 69632                      // 128 f
#define OFF_AS  (OFF_SRC + 512)
#define OFF_W2  (OFF_AS  + 512)
#define OFF_PS  (OFF_W2  + 512)            // 64*4 f
#define SMEM_BYTES (OFF_PS + 1024)

#define NTHR 256

extern __shared__ char smem_raw[];

__global__ __launch_bounds__(NTHR, 2) void edge_main_kernel(
    const float* __restrict__ W1, const float* __restrict__ W2,
    const float* __restrict__ b2p, const int* __restrict__ mask,
    float* __restrict__ out)
{
    __half* Whi = (__half*)(smem_raw + OFF_WHI);
    float* ssrc = (float*)(smem_raw + OFF_SRC);
    float* As   = (float*)(smem_raw + OFF_AS);
    float* w2s  = (float*)(smem_raw + OFF_W2);
    float* psum = (float*)(smem_raw + OFF_PS);     // [64][4]

    unsigned smem_u32;
    asm("{ .reg .u64 t; cvta.to.shared.u64 t, %1; cvt.u32.u64 %0, t; }"
        : "=r"(smem_u32) : "l"(smem_raw));

    const int bs    = blockIdx.x >> 1;       // 0..1023
    const int thalf = blockIdx.x & 1;        // 0 or 1 (t offset 0 / 256)
    const int b     = bs >> 9;
    const int tid   = threadIdx.x;
    const int wid   = tid >> 5;
    const int lane  = tid & 31;

    // Warp tiling within 64t x 128k iteration tile: 2 t-groups x 4 k-groups
    const int tw0 = (wid >> 2) * 32;    // 0 or 32
    const int kq  = (wid & 3) * 32;     // k base
    const int rL = lane & 15;
    const int cL = (lane >> 4) << 3;

    const int gtbase = (b << 9) + thalf * 256;

    // Prefetch Th(0) into buf0 (coalesced 16B cp.async) — overlaps prologue
    {
        const uint4* sth = (const uint4*)(g_th + gtbase * H);
        #pragma unroll
        for (int i = tid; i < TROWS * 16; i += NTHR) {
            const int row = i >> 4;
            const int c8  = i & 15;
            cp16(smem_u32 + OFF_TH0 + (row * PAD + c8 * 8) * 2, sth + i);
        }
        cp_commit();
    }

    if (tid < H) {
        ssrc[tid] = g_src[bs * H + tid];
        As[tid]   = g_A[bs * H + tid];
        w2s[tid]  = W2[tid];
    }
    __syncthreads();

    // Prologue: Whi[h][k] = fp16( src[h]*W1_st[h][k] + W1_t[h][k] )
    {
        const float4* Wst4 = (const float4*)(W1 + 2 * H * H);
        const float4* Wt4  = (const float4*)(W1 + 1 * H * H);
        for (int i = tid; i < (H * H) / 4; i += NTHR) {
            const int h = i >> 5;
            const int c = (i & 31) * 4;
            const float sc = ssrc[h];
            float4 w = Wst4[i];
            float4 wt = Wt4[i];
            Whi[h * PAD + c + 0] = __float2half(fmaf(w.x, sc, wt.x));
            Whi[h * PAD + c + 1] = __float2half(fmaf(w.y, sc, wt.y));
            Whi[h * PAD + c + 2] = __float2half(fmaf(w.z, sc, wt.z));
            Whi[h * PAD + c + 3] = __float2half(fmaf(w.w, sc, wt.w));
        }
    }
    __syncthreads();   // As/w2s fully written before register caching

    // Register-cache per-thread A and W2 values (iteration-invariant)
    float asr[8], w2r[8];
    #pragma unroll
    for (int g = 0; g < 4; ++g) {
        const int k = kq + g * 8 + (lane & 3) * 2;
        asr[2 * g]     = As[k];
        asr[2 * g + 1] = As[k + 1];
        w2r[2 * g]     = w2s[k];
        w2r[2 * g + 1] = w2s[k + 1];
    }

    const float b2v  = b2p[0];
    const float mval = mask[bs] ? 1.0f : 0.0f;

    #pragma unroll 1
    for (int tt = 0; tt < 4; ++tt) {
        const int gt0 = gtbase + tt * TROWS;
        const unsigned thb = smem_u32 + ((tt & 1) ? OFF_TH1 : OFF_TH0);

        cp_wait0();          // Th(tt) copies issued by this thread done
        __syncthreads();     // all threads' copies visible

        // Prefetch Th(tt+1) into the other buffer (disjoint from thb)
        if (tt < 3) {
            const unsigned thn = smem_u32 + ((tt & 1) ? OFF_TH0 : OFF_TH1);
            const uint4* sth = (const uint4*)(g_th + (gt0 + TROWS) * H);
            #pragma unroll
            for (int i = tid; i < TROWS * 16; i += NTHR) {
                const int row = i >> 4;
                const int c8  = i & 15;
                cp16(thn + (row * PAD + c8 * 8) * 2, sth + i);
            }
            cp_commit();
        }

        // Mainloop: 32t x 32k per warp, K=128 in 8 steps, single fp16 pass
        float acc[2][4][4];
        #pragma unroll
        for (int f = 0; f < 2; ++f)
            #pragma unroll
            for (int g = 0; g < 4; ++g)
                #pragma unroll
                for (int j = 0; j < 4; ++j) acc[f][g][j] = 0.f;

        #pragma unroll
        for (int step = 0; step < 8; ++step) {
            const int h0 = step * 16;
            unsigned ath[2][4];
            #pragma unroll
            for (int f = 0; f < 2; ++f) {
                unsigned addr = thb + ((tw0 + f * 16 + rL) * PAD + h0 + cL) * 2;
                ldsm_x4(addr, ath[f][0], ath[f][1], ath[f][2], ath[f][3]);
            }
            #pragma unroll
            for (int g = 0; g < 2; ++g) {
                const int nA = kq + g * 16;
                unsigned bh0, bh1, bh2, bh3;
                unsigned baddr = smem_u32 + OFF_WHI + ((h0 + rL) * PAD + nA + cL) * 2;
                ldsm_x4_t(baddr, bh0, bh1, bh2, bh3);
                #pragma unroll
                for (int f = 0; f < 2; ++f) {
                    mma16816(acc[f][2 * g],     ath[f], bh0, bh1);
                    mma16816(acc[f][2 * g + 1], ath[f], bh2, bh3);
                }
            }
        }

        // Epilogue: + A, fast exact-gelu, dot W2, quad-reduce, psum combine,
        // softsign, store.  (C-term already inside the GEMM.)
        #pragma unroll
        for (int f = 0; f < 2; ++f) {
            #pragma unroll
            for (int hf = 0; hf < 2; ++hf) {
                const int t = tw0 + f * 16 + (lane >> 2) + hf * 8;
                float pt = 0.f;
                #pragma unroll
                for (int g = 0; g < 4; ++g) {
                    float h0v = acc[f][g][hf * 2 + 0] + asr[2 * g];
                    float h1v = acc[f][g][hf * 2 + 1] + asr[2 * g + 1];
                    pt = fmaf(gelu_fast(h0v), w2r[2 * g],     pt);
                    pt = fmaf(gelu_fast(h1v), w2r[2 * g + 1], pt);
                }
                pt += __shfl_xor_sync(0xffffffffu, pt, 1);
                pt += __shfl_xor_sync(0xffffffffu, pt, 2);
                if ((lane & 3) == 0)
                    psum[t * 4 + (wid & 3)] = pt;
            }
        }
        __syncthreads();

        if (tid < TROWS) {
            const float sc = psum[tid * 4] + psum[tid * 4 + 1]
                           + psum[tid * 4 + 2] + psum[tid * 4 + 3] + b2v;
            const float e  = sc / (1.0f + fabsf(sc));
            out[bs * T + thalf * 256 + tt * TROWS + tid] = e * mval;
        }
    }
}

// ---------------------------------------------------------------------------
extern "C" void kernel_launch(void* const* d_in, const int* in_sizes, int n_in,
                              void* d_out, int out_size)
{
    const float* sv   = (const float*)d_in[0];
    const float* tv   = (const float*)d_in[1];
    const int*   mask = (const int*)d_in[2];
    const float* sng  = (const float*)d_in[3];
    const float* snb  = (const float*)d_in[4];
    const float* tng  = (const float*)d_in[5];
    const float* tnb  = (const float*)d_in[6];
    const float* Wsu  = (const float*)d_in[7];
    const float* bsu  = (const float*)d_in[8];
    const float* Wtp  = (const float*)d_in[9];
    const float* btp  = (const float*)d_in[10];
    const float* W1   = (const float*)d_in[11];
    const float* b1   = (const float*)d_in[12];
    const float* W2   = (const float*)d_in[13];
    const float* b2   = (const float*)d_in[14];
    float* out = (float*)d_out;

    norm_proj_kernel<<<BS + BT, 256>>>(sv, tv, sng, snb, tng, tnb,
                                       Wsu, bsu, Wtp, btp, W1, b1);

    cudaFuncSetAttribute(edge_main_kernel,
                         cudaFuncAttributeMaxDynamicSharedMemorySize, SMEM_BYTES);
    edge_main_kernel<<<2 * BS, NTHR, SMEM_BYTES>>>(W1, W2, b2, mask, out);
}

// round 14
// speedup vs baseline: 3.3565x; 1.1282x over previous
#include <cuda_runtime.h>
#include <cuda_fp16.h>
#include <cstdint>

// Shapes (fixed per reference setup_inputs)
#define B 2
#define S 512
#define T 512
#define D 256
#define H 128
#define BS (B*S)        // 1024
#define BT (B*T)        // 1024

#define PAD 136         // padded row stride (elems) for conflict-free ldmatrix

// Scratch (device globals; no allocation allowed)
__device__ float g_src[BS * H];       // LN(source) @ W_su + b_su (fp32)
__device__ float g_A  [BS * H];       // g_src @ W1_s + b1
__device__ __half g_th [BT * H];      // fp16 target proj

// ---------------------------------------------------------------------------
// Stage 1: per-row layernorm + projection (+ W1_s projection for source).
// ---------------------------------------------------------------------------
__global__ __launch_bounds__(256) void norm_proj_kernel(
    const float* __restrict__ sv, const float* __restrict__ tv,
    const float* __restrict__ sng, const float* __restrict__ snb,
    const float* __restrict__ tng, const float* __restrict__ tnb,
    const float* __restrict__ Wsu, const float* __restrict__ bsu,
    const float* __restrict__ Wtp, const float* __restrict__ btp,
    const float* __restrict__ W1,  const float* __restrict__ b1)
{
    __shared__ float xn[D];
    __shared__ float pr[H];
    __shared__ float r1[8], r2[8];

    const int r = blockIdx.x;
    const bool is_src = (r < BS);
    const int row = is_src ? r : r - BS;
    const int tid = threadIdx.x;

    const float* x    = (is_src ? sv : tv) + row * D;
    const float* gv   = is_src ? sng : tng;
    const float* bv   = is_src ? snb : tnb;
    const float* W    = is_src ? Wsu : Wtp;
    const float* bias = is_src ? bsu : btp;

    float v = x[tid];
    float s1 = v, s2 = v * v;
    #pragma unroll
    for (int m = 16; m; m >>= 1) {
        s1 += __shfl_xor_sync(0xffffffffu, s1, m);
        s2 += __shfl_xor_sync(0xffffffffu, s2, m);
    }
    if ((tid & 31) == 0) { r1[tid >> 5] = s1; r2[tid >> 5] = s2; }
    __syncthreads();
    float t1 = 0.f, t2 = 0.f;
    #pragma unroll
    for (int i = 0; i < 8; ++i) { t1 += r1[i]; t2 += r2[i]; }
    const float mean = t1 * (1.0f / D);
    const float var  = t2 * (1.0f / D) - mean * mean;
    const float rs   = rsqrtf(var + 1e-5f);
    xn[tid] = (v - mean) * rs * gv[tid] + bv[tid];
    __syncthreads();

    if (tid < H) {
        float a0 = 0.f, a1 = 0.f, a2 = 0.f, a3 = 0.f;
        #pragma unroll 4
        for (int d = 0; d < D; d += 4) {
            a0 = fmaf(xn[d + 0], W[(d + 0) * H + tid], a0);
            a1 = fmaf(xn[d + 1], W[(d + 1) * H + tid], a1);
            a2 = fmaf(xn[d + 2], W[(d + 2) * H + tid], a2);
            a3 = fmaf(xn[d + 3], W[(d + 3) * H + tid], a3);
        }
        float p = (a0 + a1) + (a2 + a3) + bias[tid];
        pr[tid] = p;
        if (is_src) g_src[row * H + tid] = p;
        else        g_th[row * H + tid]  = __float2half(p);
    }
    __syncthreads();

    // Only source rows need A = proj @ W1_s + b1 (C-term folded into stage 2)
    if (is_src && tid < H) {
        const float* Wr = W1;
        float a0 = 0.f, a1 = 0.f, a2 = 0.f, a3 = 0.f;
        #pragma unroll 4
        for (int h = 0; h < H; h += 4) {
            a0 = fmaf(pr[h + 0], Wr[(h + 0) * H + tid], a0);
            a1 = fmaf(pr[h + 1], Wr[(h + 1) * H + tid], a1);
            a2 = fmaf(pr[h + 2], Wr[(h + 2) * H + tid], a2);
            a3 = fmaf(pr[h + 3], Wr[(h + 3) * H + tid], a3);
        }
        g_A[row * H + tid] = (a0 + a1) + (a2 + a3) + b1[tid];
    }
}

// ---------------------------------------------------------------------------
// Packed f32x2 helpers
// ---------------------------------------------------------------------------
typedef unsigned long long u64;

__device__ __forceinline__ u64 f2x_fma(u64 a, u64 b, u64 c) {
    u64 d; asm("fma.rn.f32x2 %0, %1, %2, %3;" : "=l"(d) : "l"(a), "l"(b), "l"(c));
    return d;
}
__device__ __forceinline__ u64 f2x_mul(u64 a, u64 b) {
    u64 d; asm("mul.rn.f32x2 %0, %1, %2;" : "=l"(d) : "l"(a), "l"(b));
    return d;
}
__device__ __forceinline__ u64 f2x_add(u64 a, u64 b) {
    u64 d; asm("add.rn.f32x2 %0, %1, %2;" : "=l"(d) : "l"(a), "l"(b));
    return d;
}
__device__ __forceinline__ u64 pk2(float lo, float hi) {
    u64 d; asm("mov.b64 %0, {%1, %2};" : "=l"(d) : "f"(lo), "f"(hi));
    return d;
}
__device__ __forceinline__ u64 dup2(float c) {
    u64 d; asm("mov.b64 %0, {%1, %1};" : "=l"(d) : "f"(c));
    return d;
}
__device__ __forceinline__ void upk2(float &lo, float &hi, u64 v) {
    asm("mov.b64 {%0, %1}, %2;" : "=f"(lo), "=f"(hi) : "l"(v));
}
__device__ __forceinline__ float rcp_ap(float x) {
    float r; asm("rcp.approx.f32 %0, %1;" : "=f"(r) : "f"(x));
    return r;
}
__device__ __forceinline__ float ex2_ap(float x) {
    float r; asm("ex2.approx.f32 %0, %1;" : "=f"(r) : "f"(x));
    return r;
}

// ---------------------------------------------------------------------------
// Stage 2: mma.sync fp16 fused kernel, C-term folded into the weight.
// grid 2048: CTA = (b, s, t-half). 256 threads / 8 warps, 2 CTAs/SM.
// Epilogue gelu fully packed f32x2 (A-S erf, sign-folded, negated Horner).
// ---------------------------------------------------------------------------
__device__ __forceinline__ void ldsm_x4(unsigned a, unsigned &r0, unsigned &r1,
                                        unsigned &r2, unsigned &r3) {
    asm volatile("ldmatrix.sync.aligned.m8n8.x4.shared.b16 {%0,%1,%2,%3}, [%4];"
        : "=r"(r0), "=r"(r1), "=r"(r2), "=r"(r3) : "r"(a));
}
__device__ __forceinline__ void ldsm_x4_t(unsigned a, unsigned &r0, unsigned &r1,
                                          unsigned &r2, unsigned &r3) {
    asm volatile("ldmatrix.sync.aligned.m8n8.x4.trans.shared.b16 {%0,%1,%2,%3}, [%4];"
        : "=r"(r0), "=r"(r1), "=r"(r2), "=r"(r3) : "r"(a));
}
__device__ __forceinline__ void mma16816(float* c, const unsigned* a,
                                         unsigned b0, unsigned b1) {
    asm volatile("mma.sync.aligned.m16n8k16.row.col.f32.f16.f16.f32 "
        "{%0,%1,%2,%3}, {%4,%5,%6,%7}, {%8,%9}, {%0,%1,%2,%3};"
        : "+f"(c[0]), "+f"(c[1]), "+f"(c[2]), "+f"(c[3])
        : "r"(a[0]), "r"(a[1]), "r"(a[2]), "r"(a[3]), "r"(b0), "r"(b1));
}
__device__ __forceinline__ void cp16(unsigned dst, const void* src) {
    asm volatile("cp.async.ca.shared.global [%0], [%1], 16;"
        :: "r"(dst), "l"(src) : "memory");
}
__device__ __forceinline__ void cp_commit() {
    asm volatile("cp.async.commit_group;" ::: "memory");
}
__device__ __forceinline__ void cp_wait0() {
    asm volatile("cp.async.wait_group 0;" ::: "memory");
}

// smem byte offsets
#define TROWS 64
#define OFF_WHI 0                          // 128*136*2 = 34816
#define OFF_TH0 34816                      // 64*136*2  = 17408
#define OFF_TH1 52224                      // 17408
#define OFF_SRC 69632                      // 128 f
#define OFF_AS  (OFF_SRC + 512)
#define OFF_W2  (OFF_AS  + 512)
#define OFF_PS  (OFF_W2  + 512)            // 64*4 f
#define SMEM_BYTES (OFF_PS + 1024)

#define NTHR 256

extern __shared__ char smem_raw[];

__global__ __launch_bounds__(NTHR, 2) void edge_main_kernel(
    const float* __restrict__ W1, const float* __restrict__ W2,
    const float* __restrict__ b2p, const int* __restrict__ mask,
    float* __restrict__ out)
{
    __half* Whi = (__half*)(smem_raw + OFF_WHI);
    float* ssrc = (float*)(smem_raw + OFF_SRC);
    float* As   = (float*)(smem_raw + OFF_AS);
    float* w2s  = (float*)(smem_raw + OFF_W2);
    float* psum = (float*)(smem_raw + OFF_PS);     // [64][4]

    unsigned smem_u32;
    asm("{ .reg .u64 t; cvta.to.shared.u64 t, %1; cvt.u32.u64 %0, t; }"
        : "=r"(smem_u32) : "l"(smem_raw));

    const int bs    = blockIdx.x >> 1;       // 0..1023
    const int thalf = blockIdx.x & 1;        // 0 or 1 (t offset 0 / 256)
    const int b     = bs >> 9;
    const int tid   = threadIdx.x;
    const int wid   = tid >> 5;
    const int lane  = tid & 31;

    // Warp tiling within 64t x 128k iteration tile: 2 t-groups x 4 k-groups
    const int tw0 = (wid >> 2) * 32;    // 0 or 32
    const int kq  = (wid & 3) * 32;     // k base
    const int rL = lane & 15;
    const int cL = (lane >> 4) << 3;

    const int gtbase = (b << 9) + thalf * 256;

    // Prefetch Th(0) into buf0 (coalesced 16B cp.async) — overlaps prologue
    {
        const uint4* sth = (const uint4*)(g_th + gtbase * H);
        #pragma unroll
        for (int i = tid; i < TROWS * 16; i += NTHR) {
            const int row = i >> 4;
            const int c8  = i & 15;
            cp16(smem_u32 + OFF_TH0 + (row * PAD + c8 * 8) * 2, sth + i);
        }
        cp_commit();
    }

    if (tid < H) {
        ssrc[tid] = g_src[bs * H + tid];
        As[tid]   = g_A[bs * H + tid];
        w2s[tid]  = W2[tid];
    }
    __syncthreads();

    // Prologue: Whi[h][k] = fp16( src[h]*W1_st[h][k] + W1_t[h][k] )
    {
        const float4* Wst4 = (const float4*)(W1 + 2 * H * H);
        const float4* Wt4  = (const float4*)(W1 + 1 * H * H);
        for (int i = tid; i < (H * H) / 4; i += NTHR) {
            const int h = i >> 5;
            const int c = (i & 31) * 4;
            const float sc = ssrc[h];
            float4 w = Wst4[i];
            float4 wt = Wt4[i];
            Whi[h * PAD + c + 0] = __float2half(fmaf(w.x, sc, wt.x));
            Whi[h * PAD + c + 1] = __float2half(fmaf(w.y, sc, wt.y));
            Whi[h * PAD + c + 2] = __float2half(fmaf(w.z, sc, wt.z));
            Whi[h * PAD + c + 3] = __float2half(fmaf(w.w, sc, wt.w));
        }
    }
    __syncthreads();   // As/w2s fully written before register caching

    // Register-cache per-thread A and W2 pairs (packed f32x2, iter-invariant)
    u64 asr2[4], w2r2[4];
    #pragma unroll
    for (int g = 0; g < 4; ++g) {
        const int k = kq + g * 8 + (lane & 3) * 2;
        asr2[g] = pk2(As[k], As[k + 1]);
        w2r2[g] = pk2(w2s[k], w2s[k + 1]);
    }

    // Packed gelu constants (A-S 7.1.26, sign-folded, negated Horner)
    const u64 C_A  = dup2(0.23164192f);     // 0.3275911 / sqrt(2)
    const u64 C_1  = dup2(1.0f);
    const u64 C_H  = dup2(0.5f);
    const u64 C_NL = dup2(-0.72134752f);    // -log2(e)/2
    const u64 C_K1 = dup2(-1.061405429f);
    const u64 C_K2 = dup2( 1.453152027f);
    const u64 C_K3 = dup2(-1.421413741f);
    const u64 C_K4 = dup2( 0.284496736f);
    const u64 C_K5 = dup2(-0.254829592f);

    const float b2v  = b2p[0];
    const float mval = mask[bs] ? 1.0f : 0.0f;

    #pragma unroll 1
    for (int tt = 0; tt < 4; ++tt) {
        const int gt0 = gtbase + tt * TROWS;
        const unsigned thb = smem_u32 + ((tt & 1) ? OFF_TH1 : OFF_TH0);

        cp_wait0();          // Th(tt) copies issued by this thread done
        __syncthreads();     // all threads' copies visible

        // Prefetch Th(tt+1) into the other buffer (disjoint from thb)
        if (tt < 3) {
            const unsigned thn = smem_u32 + ((tt & 1) ? OFF_TH0 : OFF_TH1);
            const uint4* sth = (const uint4*)(g_th + (gt0 + TROWS) * H);
            #pragma unroll
            for (int i = tid; i < TROWS * 16; i += NTHR) {
                const int row = i >> 4;
                const int c8  = i & 15;
                cp16(thn + (row * PAD + c8 * 8) * 2, sth + i);
            }
            cp_commit();
        }

        // Mainloop: 32t x 32k per warp, K=128 in 8 steps, single fp16 pass
        float acc[2][4][4];
        #pragma unroll
        for (int f = 0; f < 2; ++f)
            #pragma unroll
            for (int g = 0; g < 4; ++g)
                #pragma unroll
                for (int j = 0; j < 4; ++j) acc[f][g][j] = 0.f;

        #pragma unroll
        for (int step = 0; step < 8; ++step) {
            const int h0 = step * 16;
            unsigned ath[2][4];
            #pragma unroll
            for (int f = 0; f < 2; ++f) {
                unsigned addr = thb + ((tw0 + f * 16 + rL) * PAD + h0 + cL) * 2;
                ldsm_x4(addr, ath[f][0], ath[f][1], ath[f][2], ath[f][3]);
            }
            #pragma unroll
            for (int g = 0; g < 2; ++g) {
                const int nA = kq + g * 16;
                unsigned bh0, bh1, bh2, bh3;
                unsigned baddr = smem_u32 + OFF_WHI + ((h0 + rL) * PAD + nA + cL) * 2;
                ldsm_x4_t(baddr, bh0, bh1, bh2, bh3);
                #pragma unroll
                for (int f = 0; f < 2; ++f) {
                    mma16816(acc[f][2 * g],     ath[f], bh0, bh1);
                    mma16816(acc[f][2 * g + 1], ath[f], bh2, bh3);
                }
            }
        }

        // Epilogue: packed f32x2 gelu + W2-dot, quad-reduce, psum, softsign.
        // gelu(x) = 0.5x + q + q*(p'(t)*e), q=0.5|x|, t=1/(1+a|x|/sqrt2),
        //           e=2^(-x^2 * log2e/2), p' = negated A-S Horner poly.
        #pragma unroll
        for (int f = 0; f < 2; ++f) {
            #pragma unroll
            for (int hf = 0; hf < 2; ++hf) {
                const int t = tw0 + f * 16 + (lane >> 2) + hf * 8;
                u64 pt2 = 0ULL;
                #pragma unroll
                for (int g = 0; g < 4; ++g) {
                    u64 x2 = pk2(acc[f][g][hf * 2 + 0], acc[f][g][hf * 2 + 1]);
                    x2 = f2x_add(x2, asr2[g]);
                    const u64 ax2 = x2 & 0x7FFFFFFF7FFFFFFFULL;
                    const u64 d2 = f2x_fma(C_A, ax2, C_1);
                    const u64 s2 = f2x_mul(ax2, ax2);
                    const u64 y2 = f2x_mul(s2, C_NL);
                    float dl, dh;  upk2(dl, dh, d2);
                    const u64 t2 = pk2(rcp_ap(dl), rcp_ap(dh));
                    float yl, yh;  upk2(yl, yh, y2);
                    const u64 e2 = pk2(ex2_ap(yl), ex2_ap(yh));
                    u64 p2 = f2x_fma(C_K1, t2, C_K2);
                    p2 = f2x_fma(p2, t2, C_K3);
                    p2 = f2x_fma(p2, t2, C_K4);
                    p2 = f2x_fma(p2, t2, C_K5);
                    p2 = f2x_mul(p2, t2);
                    const u64 m2 = f2x_mul(p2, e2);
                    const u64 q2 = f2x_mul(ax2, C_H);
                    const u64 bb = f2x_fma(x2, C_H, q2);
                    const u64 r2 = f2x_fma(m2, q2, bb);
                    pt2 = f2x_fma(r2, w2r2[g], pt2);
                }
                float plo, phi; upk2(plo, phi, pt2);
                float pt = plo + phi;
                pt += __shfl_xor_sync(0xffffffffu, pt, 1);
                pt += __shfl_xor_sync(0xffffffffu, pt, 2);
                if ((lane & 3) == 0)
                    psum[t * 4 + (wid & 3)] = pt;
            }
        }
        __syncthreads();

        if (tid < TROWS) {
            const float sc = psum[tid * 4] + psum[tid * 4 + 1]
                           + psum[tid * 4 + 2] + psum[tid * 4 + 3] + b2v;
            const float e  = sc / (1.0f + fabsf(sc));
            out[bs * T + thalf * 256 + tt * TROWS + tid] = e * mval;
        }
    }
}

// ---------------------------------------------------------------------------
extern "C" void kernel_launch(void* const* d_in, const int* in_sizes, int n_in,
                              void* d_out, int out_size)
{
    const float* sv   = (const float*)d_in[0];
    const float* tv   = (const float*)d_in[1];
    const int*   mask = (const int*)d_in[2];
    const float* sng  = (const float*)d_in[3];
    const float* snb  = (const float*)d_in[4];
    const float* tng  = (const float*)d_in[5];
    const float* tnb  = (const float*)d_in[6];
    const float* Wsu  = (const float*)d_in[7];
    const float* bsu  = (const float*)d_in[8];
    const float* Wtp  = (const float*)d_in[9];
    const float* btp  = (const float*)d_in[10];
    const float* W1   = (const float*)d_in[11];
    const float* b1   = (const float*)d_in[12];
    const float* W2   = (const float*)d_in[13];
    const float* b2   = (const float*)d_in[14];
    float* out = (float*)d_out;

    norm_proj_kernel<<<BS + BT, 256>>>(sv, tv, sng, snb, tng, tnb,
                                       Wsu, bsu, Wtp, btp, W1, b1);

    cudaFuncSetAttribute(edge_main_kernel,
                         cudaFuncAttributeMaxDynamicSharedMemorySize, SMEM_BYTES);
    edge_main_kernel<<<2 * BS, NTHR, SMEM_BYTES>>>(W1, W2, b2, mask, out);
}

// round 15
// speedup vs baseline: 3.5364x; 1.0536x over previous
#include <cuda_runtime.h>
#include <cuda_fp16.h>
#include <cstdint>

// Shapes (fixed per reference setup_inputs)
#define B 2
#define S 512
#define T 512
#define D 256
#define H 128
#define BS (B*S)        // 1024
#define BT (B*T)        // 1024

#define PAD 136         // padded row stride (elems) for conflict-free ldmatrix

// Scratch (device globals; no allocation allowed)
__device__ float g_src[BS * H];       // LN(source) @ W_su + b_su (fp32)
__device__ float g_A  [BS * H];       // g_src @ W1_s + b1
__device__ __half g_th [BT * H];      // fp16 target proj

// ---------------------------------------------------------------------------
// Packed f32x2 helpers
// ---------------------------------------------------------------------------
typedef unsigned long long u64;

__device__ __forceinline__ u64 f2x_fma(u64 a, u64 b, u64 c) {
    u64 d; asm("fma.rn.f32x2 %0, %1, %2, %3;" : "=l"(d) : "l"(a), "l"(b), "l"(c));
    return d;
}
__device__ __forceinline__ u64 f2x_mul(u64 a, u64 b) {
    u64 d; asm("mul.rn.f32x2 %0, %1, %2;" : "=l"(d) : "l"(a), "l"(b));
    return d;
}
__device__ __forceinline__ u64 f2x_add(u64 a, u64 b) {
    u64 d; asm("add.rn.f32x2 %0, %1, %2;" : "=l"(d) : "l"(a), "l"(b));
    return d;
}
__device__ __forceinline__ u64 pk2(float lo, float hi) {
    u64 d; asm("mov.b64 %0, {%1, %2};" : "=l"(d) : "f"(lo), "f"(hi));
    return d;
}
__device__ __forceinline__ u64 dup2(float c) {
    u64 d; asm("mov.b64 %0, {%1, %1};" : "=l"(d) : "f"(c));
    return d;
}
__device__ __forceinline__ void upk2(float &lo, float &hi, u64 v) {
    asm("mov.b64 {%0, %1}, %2;" : "=f"(lo), "=f"(hi) : "l"(v));
}
__device__ __forceinline__ float rcp_ap(float x) {
    float r; asm("rcp.approx.f32 %0, %1;" : "=f"(r) : "f"(x));
    return r;
}
__device__ __forceinline__ float ex2_ap(float x) {
    float r; asm("ex2.approx.f32 %0, %1;" : "=f"(r) : "f"(x));
    return r;
}

// ---------------------------------------------------------------------------
// Stage 1: 8 rows per CTA. LN per warp, packed-pair projection so each W
// element is read once per CTA (8x traffic reduction vs per-row CTAs).
// Grid: 256 = 128 source-CTAs + 128 target-CTAs.
// ---------------------------------------------------------------------------
#define RPB 8

__global__ __launch_bounds__(256) void norm_proj_kernel(
    const float* __restrict__ sv, const float* __restrict__ tv,
    const float* __restrict__ sng, const float* __restrict__ snb,
    const float* __restrict__ tng, const float* __restrict__ tnb,
    const float* __restrict__ Wsu, const float* __restrict__ bsu,
    const float* __restrict__ Wtp, const float* __restrict__ btp,
    const float* __restrict__ W1,  const float* __restrict__ b1)
{
    __shared__ u64  xnp[D * 5];          // [d][rp] pairs, stride-5 anti-conflict
    __shared__ u64  prp[H * 5];          // [h][rp] pairs
    __shared__ float part[2][RPB][H];

    const int cb = blockIdx.x;
    const bool is_src = cb < (BS / RPB);
    const int row0 = (is_src ? cb : cb - BS / RPB) * RPB;
    const int tid = threadIdx.x;
    const int wid = tid >> 5;
    const int lane = tid & 31;

    const float* x    = (is_src ? sv : tv) + row0 * D;
    const float* gv   = is_src ? sng : tng;
    const float* bv   = is_src ? snb : tnb;
    const float* W    = is_src ? Wsu : Wtp;
    const float* bias = is_src ? bsu : btp;

    // LN: warp wid handles row (row0 + wid)
    {
        const float* xr = x + wid * D;
        float v[8];
        float s1 = 0.f, s2 = 0.f;
        #pragma unroll
        for (int i = 0; i < 8; ++i) {
            float t = xr[lane + i * 32];
            v[i] = t; s1 += t; s2 = fmaf(t, t, s2);
        }
        #pragma unroll
        for (int m = 16; m; m >>= 1) {
            s1 += __shfl_xor_sync(0xffffffffu, s1, m);
            s2 += __shfl_xor_sync(0xffffffffu, s2, m);
        }
        const float mean = s1 * (1.0f / D);
        const float var  = s2 * (1.0f / D) - mean * mean;
        const float rs   = rsqrtf(var + 1e-5f);
        float* xf = (float*)xnp;
        #pragma unroll
        for (int i = 0; i < 8; ++i) {
            const int col = lane + i * 32;
            const float xv = (v[i] - mean) * rs * gv[col] + bv[col];
            xf[(col * 5 + (wid >> 1)) * 2 + (wid & 1)] = xv;
        }
    }
    __syncthreads();

    const int hh   = tid & 127;
    const int half = tid >> 7;

    // Projection: out[r][hh] over d-half, 8 rows per W element
    {
        u64 acc[4] = {0ULL, 0ULL, 0ULL, 0ULL};
        const float* Wp = W + (half * 128) * H + hh;
        #pragma unroll 4
        for (int d = 0; d < 128; ++d) {
            const u64 w2 = dup2(Wp[d * H]);
            const u64* xp = &xnp[(half * 128 + d) * 5];
            acc[0] = f2x_fma(xp[0], w2, acc[0]);
            acc[1] = f2x_fma(xp[1], w2, acc[1]);
            acc[2] = f2x_fma(xp[2], w2, acc[2]);
            acc[3] = f2x_fma(xp[3], w2, acc[3]);
        }
        #pragma unroll
        for (int rp = 0; rp < 4; ++rp) {
            float lo, hi; upk2(lo, hi, acc[rp]);
            part[half][2 * rp][hh]     = lo;
            part[half][2 * rp + 1][hh] = hi;
        }
    }
    __syncthreads();

    if (half == 0) {
        float* pf = (float*)prp;
        #pragma unroll
        for (int r = 0; r < RPB; ++r) {
            const float p = part[0][r][hh] + part[1][r][hh] + bias[hh];
            if (is_src) {
                g_src[(row0 + r) * H + hh] = p;
                pf[(hh * 5 + (r >> 1)) * 2 + (r & 1)] = p;
            } else {
                g_th[(row0 + r) * H + hh] = __float2half(p);
            }
        }
    }
    __syncthreads();

    // A = proj @ W1_s + b1 (source rows only; C-term folded into stage 2)
    if (is_src) {
        u64 acc[4] = {0ULL, 0ULL, 0ULL, 0ULL};
        const float* Wr = W1 + (half * 64) * H + hh;
        #pragma unroll 4
        for (int h = 0; h < 64; ++h) {
            const u64 w2 = dup2(Wr[h * H]);
            const u64* pp = &prp[(half * 64 + h) * 5];
            acc[0] = f2x_fma(pp[0], w2, acc[0]);
            acc[1] = f2x_fma(pp[1], w2, acc[1]);
            acc[2] = f2x_fma(pp[2], w2, acc[2]);
            acc[3] = f2x_fma(pp[3], w2, acc[3]);
        }
        #pragma unroll
        for (int rp = 0; rp < 4; ++rp) {
            float lo, hi; upk2(lo, hi, acc[rp]);
            part[half][2 * rp][hh]     = lo;
            part[half][2 * rp + 1][hh] = hi;
        }
        __syncthreads();
        if (half == 0) {
            #pragma unroll
            for (int r = 0; r < RPB; ++r)
                g_A[(row0 + r) * H + hh] =
                    part[0][r][hh] + part[1][r][hh] + b1[hh];
        }
    }
}

// ---------------------------------------------------------------------------
// Stage 2: mma.sync fp16 fused kernel, C-term folded into the weight.
// grid 2048: CTA = (b, s, t-half). 256 threads / 8 warps, 2 CTAs/SM.
// Epilogue gelu fully packed f32x2 (A-S erf, sign-folded, negated Horner).
// ---------------------------------------------------------------------------
__device__ __forceinline__ void ldsm_x4(unsigned a, unsigned &r0, unsigned &r1,
                                        unsigned &r2, unsigned &r3) {
    asm volatile("ldmatrix.sync.aligned.m8n8.x4.shared.b16 {%0,%1,%2,%3}, [%4];"
        : "=r"(r0), "=r"(r1), "=r"(r2), "=r"(r3) : "r"(a));
}
__device__ __forceinline__ void ldsm_x4_t(unsigned a, unsigned &r0, unsigned &r1,
                                          unsigned &r2, unsigned &r3) {
    asm volatile("ldmatrix.sync.aligned.m8n8.x4.trans.shared.b16 {%0,%1,%2,%3}, [%4];"
        : "=r"(r0), "=r"(r1), "=r"(r2), "=r"(r3) : "r"(a));
}
__device__ __forceinline__ void mma16816(float* c, const unsigned* a,
                                         unsigned b0, unsigned b1) {
    asm volatile("mma.sync.aligned.m16n8k16.row.col.f32.f16.f16.f32 "
        "{%0,%1,%2,%3}, {%4,%5,%6,%7}, {%8,%9}, {%0,%1,%2,%3};"
        : "+f"(c[0]), "+f"(c[1]), "+f"(c[2]), "+f"(c[3])
        : "r"(a[0]), "r"(a[1]), "r"(a[2]), "r"(a[3]), "r"(b0), "r"(b1));
}
__device__ __forceinline__ void cp16(unsigned dst, const void* src) {
    asm volatile("cp.async.ca.shared.global [%0], [%1], 16;"
        :: "r"(dst), "l"(src) : "memory");
}
__device__ __forceinline__ void cp_commit() {
    asm volatile("cp.async.commit_group;" ::: "memory");
}
__device__ __forceinline__ void cp_wait0() {
    asm volatile("cp.async.wait_group 0;" ::: "memory");
}

// smem byte offsets
#define TROWS 64
#define OFF_WHI 0                          // 128*136*2 = 34816
#define OFF_TH0 34816                      // 64*136*2  = 17408
#define OFF_TH1 52224                      // 17408
#define OFF_SRC 69632                      // 128 f
#define OFF_AS  (OFF_SRC + 512)
#define OFF_W2  (OFF_AS  + 512)
#define OFF_PS  (OFF_W2  + 512)            // 64*4 f
#define SMEM_BYTES (OFF_PS + 1024)

#define NTHR 256

extern __shared__ char smem_raw[];

__global__ __launch_bounds__(NTHR, 2) void edge_main_kernel(
    const float* __restrict__ W1, const float* __restrict__ W2,
    const float* __restrict__ b2p, const int* __restrict__ mask,
    float* __restrict__ out)
{
    __half* Whi = (__half*)(smem_raw + OFF_WHI);
    float* ssrc = (float*)(smem_raw + OFF_SRC);
    float* As   = (float*)(smem_raw + OFF_AS);
    float* w2s  = (float*)(smem_raw + OFF_W2);
    float* psum = (float*)(smem_raw + OFF_PS);     // [64][4]

    unsigned smem_u32;
    asm("{ .reg .u64 t; cvta.to.shared.u64 t, %1; cvt.u32.u64 %0, t; }"
        : "=r"(smem_u32) : "l"(smem_raw));

    const int bs    = blockIdx.x >> 1;       // 0..1023
    const int thalf = blockIdx.x & 1;        // 0 or 1 (t offset 0 / 256)
    const int b     = bs >> 9;
    const int tid   = threadIdx.x;
    const int wid   = tid >> 5;
    const int lane  = tid & 31;

    // Warp tiling within 64t x 128k iteration tile: 2 t-groups x 4 k-groups
    const int tw0 = (wid >> 2) * 32;    // 0 or 32
    const int kq  = (wid & 3) * 32;     // k base
    const int rL = lane & 15;
    const int cL = (lane >> 4) << 3;

    const int gtbase = (b << 9) + thalf * 256;

    // Prefetch Th(0) into buf0 (coalesced 16B cp.async) — overlaps prologue
    {
        const uint4* sth = (const uint4*)(g_th + gtbase * H);
        #pragma unroll
        for (int i = tid; i < TROWS * 16; i += NTHR) {
            const int row = i >> 4;
            const int c8  = i & 15;
            cp16(smem_u32 + OFF_TH0 + (row * PAD + c8 * 8) * 2, sth + i);
        }
        cp_commit();
    }

    if (tid < H) {
        ssrc[tid] = g_src[bs * H + tid];
        As[tid]   = g_A[bs * H + tid];
        w2s[tid]  = W2[tid];
    }
    __syncthreads();

    // Prologue: Whi[h][k] = fp16( src[h]*W1_st[h][k] + W1_t[h][k] )
    {
        const float4* Wst4 = (const float4*)(W1 + 2 * H * H);
        const float4* Wt4  = (const float4*)(W1 + 1 * H * H);
        for (int i = tid; i < (H * H) / 4; i += NTHR) {
            const int h = i >> 5;
            const int c = (i & 31) * 4;
            const float sc = ssrc[h];
            float4 w = Wst4[i];
            float4 wt = Wt4[i];
            Whi[h * PAD + c + 0] = __float2half(fmaf(w.x, sc, wt.x));
            Whi[h * PAD + c + 1] = __float2half(fmaf(w.y, sc, wt.y));
            Whi[h * PAD + c + 2] = __float2half(fmaf(w.z, sc, wt.z));
            Whi[h * PAD + c + 3] = __float2half(fmaf(w.w, sc, wt.w));
        }
    }
    __syncthreads();   // As/w2s fully written before register caching

    // Register-cache per-thread A and W2 pairs (packed f32x2, iter-invariant)
    u64 asr2[4], w2r2[4];
    #pragma unroll
    for (int g = 0; g < 4; ++g) {
        const int k = kq + g * 8 + (lane & 3) * 2;
        asr2[g] = pk2(As[k], As[k + 1]);
        w2r2[g] = pk2(w2s[k], w2s[k + 1]);
    }

    // Packed gelu constants (A-S 7.1.26, sign-folded, negated Horner)
    const u64 C_A  = dup2(0.23164192f);     // 0.3275911 / sqrt(2)
    const u64 C_1  = dup2(1.0f);
    const u64 C_H  = dup2(0.5f);
    const u64 C_NL = dup2(-0.72134752f);    // -log2(e)/2
    const u64 C_K1 = dup2(-1.061405429f);
    const u64 C_K2 = dup2( 1.453152027f);
    const u64 C_K3 = dup2(-1.421413741f);
    const u64 C_K4 = dup2( 0.284496736f);
    const u64 C_K5 = dup2(-0.254829592f);

    const float b2v  = b2p[0];
    const float mval = mask[bs] ? 1.0f : 0.0f;

    #pragma unroll 1
    for (int tt = 0; tt < 4; ++tt) {
        const int gt0 = gtbase + tt * TROWS;
        const unsigned thb = smem_u32 + ((tt & 1) ? OFF_TH1 : OFF_TH0);

        cp_wait0();          // Th(tt) copies issued by this thread done
        __syncthreads();     // all threads' copies visible

        // Prefetch Th(tt+1) into the other buffer (disjoint from thb)
        if (tt < 3) {
            const unsigned thn = smem_u32 + ((tt & 1) ? OFF_TH0 : OFF_TH1);
            const uint4* sth = (const uint4*)(g_th + (gt0 + TROWS) * H);
            #pragma unroll
            for (int i = tid; i < TROWS * 16; i += NTHR) {
                const int row = i >> 4;
                const int c8  = i & 15;
                cp16(thn + (row * PAD + c8 * 8) * 2, sth + i);
            }
            cp_commit();
        }

        // Mainloop: 32t x 32k per warp, K=128 in 8 steps, single fp16 pass
        float acc[2][4][4];
        #pragma unroll
        for (int f = 0; f < 2; ++f)
            #pragma unroll
            for (int g = 0; g < 4; ++g)
                #pragma unroll
                for (int j = 0; j < 4; ++j) acc[f][g][j] = 0.f;

        #pragma unroll
        for (int step = 0; step < 8; ++step) {
            const int h0 = step * 16;
            unsigned ath[2][4];
            #pragma unroll
            for (int f = 0; f < 2; ++f) {
                unsigned addr = thb + ((tw0 + f * 16 + rL) * PAD + h0 + cL) * 2;
                ldsm_x4(addr, ath[f][0], ath[f][1], ath[f][2], ath[f][3]);
            }
            #pragma unroll
            for (int g = 0; g < 2; ++g) {
                const int nA = kq + g * 16;
                unsigned bh0, bh1, bh2, bh3;
                unsigned baddr = smem_u32 + OFF_WHI + ((h0 + rL) * PAD + nA + cL) * 2;
                ldsm_x4_t(baddr, bh0, bh1, bh2, bh3);
                #pragma unroll
                for (int f = 0; f < 2; ++f) {
                    mma16816(acc[f][2 * g],     ath[f], bh0, bh1);
                    mma16816(acc[f][2 * g + 1], ath[f], bh2, bh3);
                }
            }
        }

        // Epilogue: packed f32x2 gelu + W2-dot, quad-reduce, psum, softsign.
        #pragma unroll
        for (int f = 0; f < 2; ++f) {
            #pragma unroll
            for (int hf = 0; hf < 2; ++hf) {
                const int t = tw0 + f * 16 + (lane >> 2) + hf * 8;
                u64 pt2 = 0ULL;
                #pragma unroll
                for (int g = 0; g < 4; ++g) {
                    u64 x2 = pk2(acc[f][g][hf * 2 + 0], acc[f][g][hf * 2 + 1]);
                    x2 = f2x_add(x2, asr2[g]);
                    const u64 ax2 = x2 & 0x7FFFFFFF7FFFFFFFULL;
                    const u64 d2 = f2x_fma(C_A, ax2, C_1);
                    const u64 s2 = f2x_mul(ax2, ax2);
                    const u64 y2 = f2x_mul(s2, C_NL);
                    float dl, dh;  upk2(dl, dh, d2);
                    const u64 t2 = pk2(rcp_ap(dl), rcp_ap(dh));
                    float yl, yh;  upk2(yl, yh, y2);
                    const u64 e2 = pk2(ex2_ap(yl), ex2_ap(yh));
                    u64 p2 = f2x_fma(C_K1, t2, C_K2);
                    p2 = f2x_fma(p2, t2, C_K3);
                    p2 = f2x_fma(p2, t2, C_K4);
                    p2 = f2x_fma(p2, t2, C_K5);
                    p2 = f2x_mul(p2, t2);
                    const u64 m2 = f2x_mul(p2, e2);
                    const u64 q2 = f2x_mul(ax2, C_H);
                    const u64 bb = f2x_fma(x2, C_H, q2);
                    const u64 r2 = f2x_fma(m2, q2, bb);
                    pt2 = f2x_fma(r2, w2r2[g], pt2);
                }
                float plo, phi; upk2(plo, phi, pt2);
                float pt = plo + phi;
                pt += __shfl_xor_sync(0xffffffffu, pt, 1);
                pt += __shfl_xor_sync(0xffffffffu, pt, 2);
                if ((lane & 3) == 0)
                    psum[t * 4 + (wid & 3)] = pt;
            }
        }
        __syncthreads();

        if (tid < TROWS) {
            const float sc = psum[tid * 4] + psum[tid * 4 + 1]
                           + psum[tid * 4 + 2] + psum[tid * 4 + 3] + b2v;
            const float e  = sc / (1.0f + fabsf(sc));
            out[bs * T + thalf * 256 + tt * TROWS + tid] = e * mval;
        }
    }
}

// ---------------------------------------------------------------------------
extern "C" void kernel_launch(void* const* d_in, const int* in_sizes, int n_in,
                              void* d_out, int out_size)
{
    const float* sv   = (const float*)d_in[0];
    const float* tv   = (const float*)d_in[1];
    const int*   mask = (const int*)d_in[2];
    const float* sng  = (const float*)d_in[3];
    const float* snb  = (const float*)d_in[4];
    const float* tng  = (const float*)d_in[5];
    const float* tnb  = (const float*)d_in[6];
    const float* Wsu  = (const float*)d_in[7];
    const float* bsu  = (const float*)d_in[8];
    const float* Wtp  = (const float*)d_in[9];
    const float* btp  = (const float*)d_in[10];
    const float* W1   = (const float*)d_in[11];
    const float* b1   = (const float*)d_in[12];
    const float* W2   = (const float*)d_in[13];
    const float* b2   = (const float*)d_in[14];
    float* out = (float*)d_out;

    norm_proj_kernel<<<(BS + BT) / RPB, 256>>>(sv, tv, sng, snb, tng, tnb,
                                               Wsu, bsu, Wtp, btp, W1, b1);

    cudaFuncSetAttribute(edge_main_kernel,
                         cudaFuncAttributeMaxDynamicSharedMemorySize, SMEM_BYTES);
    edge_main_kernel<<<2 * BS, NTHR, SMEM_BYTES>>>(W1, W2, b2, mask, out);
}

// round 16
// speedup vs baseline: 3.5944x; 1.0164x over previous
#include <cuda_runtime.h>
#include <cuda_fp16.h>
#include <cstdint>

// Shapes (fixed per reference setup_inputs)
#define B 2
#define S 512
#define T 512
#define D 256
#define H 128
#define BS (B*S)        // 1024
#define BT (B*T)        // 1024

#define PAD 136         // padded row stride (elems) for conflict-free ldmatrix

// Scratch (device globals; no allocation allowed)
__device__ float g_src[BS * H];       // LN(source) @ W_su + b_su (fp32)
__device__ float g_A  [BS * H];       // g_src @ W1_s + b1
__device__ __half g_th [BT * H];      // fp16 target proj

// ---------------------------------------------------------------------------
// Packed f32x2 helpers
// ---------------------------------------------------------------------------
typedef unsigned long long u64;

__device__ __forceinline__ u64 f2x_fma(u64 a, u64 b, u64 c) {
    u64 d; asm("fma.rn.f32x2 %0, %1, %2, %3;" : "=l"(d) : "l"(a), "l"(b), "l"(c));
    return d;
}
__device__ __forceinline__ u64 f2x_mul(u64 a, u64 b) {
    u64 d; asm("mul.rn.f32x2 %0, %1, %2;" : "=l"(d) : "l"(a), "l"(b));
    return d;
}
__device__ __forceinline__ u64 f2x_add(u64 a, u64 b) {
    u64 d; asm("add.rn.f32x2 %0, %1, %2;" : "=l"(d) : "l"(a), "l"(b));
    return d;
}
__device__ __forceinline__ u64 pk2(float lo, float hi) {
    u64 d; asm("mov.b64 %0, {%1, %2};" : "=l"(d) : "f"(lo), "f"(hi));
    return d;
}
__device__ __forceinline__ u64 dup2(float c) {
    u64 d; asm("mov.b64 %0, {%1, %1};" : "=l"(d) : "f"(c));
    return d;
}
__device__ __forceinline__ void upk2(float &lo, float &hi, u64 v) {
    asm("mov.b64 {%0, %1}, %2;" : "=f"(lo), "=f"(hi) : "l"(v));
}
__device__ __forceinline__ float rcp_ap(float x) {
    float r; asm("rcp.approx.f32 %0, %1;" : "=f"(r) : "f"(x));
    return r;
}
__device__ __forceinline__ float ex2_ap(float x) {
    float r; asm("ex2.approx.f32 %0, %1;" : "=f"(r) : "f"(x));
    return r;
}

// ---------------------------------------------------------------------------
// Stage 1: 8 rows per CTA. LN per warp, packed-pair projection so each W
// element is read once per CTA (8x traffic reduction vs per-row CTAs).
// Grid: 256 = 128 source-CTAs + 128 target-CTAs.
// ---------------------------------------------------------------------------
#define RPB 8

__global__ __launch_bounds__(256) void norm_proj_kernel(
    const float* __restrict__ sv, const float* __restrict__ tv,
    const float* __restrict__ sng, const float* __restrict__ snb,
    const float* __restrict__ tng, const float* __restrict__ tnb,
    const float* __restrict__ Wsu, const float* __restrict__ bsu,
    const float* __restrict__ Wtp, const float* __restrict__ btp,
    const float* __restrict__ W1,  const float* __restrict__ b1)
{
    __shared__ u64  xnp[D * 5];          // [d][rp] pairs, stride-5 anti-conflict
    __shared__ u64  prp[H * 5];          // [h][rp] pairs
    __shared__ float part[2][RPB][H];

    const int cb = blockIdx.x;
    const bool is_src = cb < (BS / RPB);
    const int row0 = (is_src ? cb : cb - BS / RPB) * RPB;
    const int tid = threadIdx.x;
    const int wid = tid >> 5;
    const int lane = tid & 31;

    const float* x    = (is_src ? sv : tv) + row0 * D;
    const float* gv   = is_src ? sng : tng;
    const float* bv   = is_src ? snb : tnb;
    const float* W    = is_src ? Wsu : Wtp;
    const float* bias = is_src ? bsu : btp;

    // LN: warp wid handles row (row0 + wid)
    {
        const float* xr = x + wid * D;
        float v[8];
        float s1 = 0.f, s2 = 0.f;
        #pragma unroll
        for (int i = 0; i < 8; ++i) {
            float t = xr[lane + i * 32];
            v[i] = t; s1 += t; s2 = fmaf(t, t, s2);
        }
        #pragma unroll
        for (int m = 16; m; m >>= 1) {
            s1 += __shfl_xor_sync(0xffffffffu, s1, m);
            s2 += __shfl_xor_sync(0xffffffffu, s2, m);
        }
        const float mean = s1 * (1.0f / D);
        const float var  = s2 * (1.0f / D) - mean * mean;
        const float rs   = rsqrtf(var + 1e-5f);
        float* xf = (float*)xnp;
        #pragma unroll
        for (int i = 0; i < 8; ++i) {
            const int col = lane + i * 32;
            const float xv = (v[i] - mean) * rs * gv[col] + bv[col];
            xf[(col * 5 + (wid >> 1)) * 2 + (wid & 1)] = xv;
        }
    }
    __syncthreads();

    const int hh   = tid & 127;
    const int half = tid >> 7;

    // Projection: out[r][hh] over d-half, 8 rows per W element
    {
        u64 acc[4] = {0ULL, 0ULL, 0ULL, 0ULL};
        const float* Wp = W + (half * 128) * H + hh;
        #pragma unroll 4
        for (int d = 0; d < 128; ++d) {
            const u64 w2 = dup2(Wp[d * H]);
            const u64* xp = &xnp[(half * 128 + d) * 5];
            acc[0] = f2x_fma(xp[0], w2, acc[0]);
            acc[1] = f2x_fma(xp[1], w2, acc[1]);
            acc[2] = f2x_fma(xp[2], w2, acc[2]);
            acc[3] = f2x_fma(xp[3], w2, acc[3]);
        }
        #pragma unroll
        for (int rp = 0; rp < 4; ++rp) {
            float lo, hi; upk2(lo, hi, acc[rp]);
            part[half][2 * rp][hh]     = lo;
            part[half][2 * rp + 1][hh] = hi;
        }
    }
    __syncthreads();

    if (half == 0) {
        float* pf = (float*)prp;
        #pragma unroll
        for (int r = 0; r < RPB; ++r) {
            const float p = part[0][r][hh] + part[1][r][hh] + bias[hh];
            if (is_src) {
                g_src[(row0 + r) * H + hh] = p;
                pf[(hh * 5 + (r >> 1)) * 2 + (r & 1)] = p;
            } else {
                g_th[(row0 + r) * H + hh] = __float2half(p);
            }
        }
    }
    __syncthreads();

    // A = proj @ W1_s + b1 (source rows only; C-term folded into stage 2)
    if (is_src) {
        u64 acc[4] = {0ULL, 0ULL, 0ULL, 0ULL};
        const float* Wr = W1 + (half * 64) * H + hh;
        #pragma unroll 4
        for (int h = 0; h < 64; ++h) {
            const u64 w2 = dup2(Wr[h * H]);
            const u64* pp = &prp[(half * 64 + h) * 5];
            acc[0] = f2x_fma(pp[0], w2, acc[0]);
            acc[1] = f2x_fma(pp[1], w2, acc[1]);
            acc[2] = f2x_fma(pp[2], w2, acc[2]);
            acc[3] = f2x_fma(pp[3], w2, acc[3]);
        }
        #pragma unroll
        for (int rp = 0; rp < 4; ++rp) {
            float lo, hi; upk2(lo, hi, acc[rp]);
            part[half][2 * rp][hh]     = lo;
            part[half][2 * rp + 1][hh] = hi;
        }
        __syncthreads();
        if (half == 0) {
            #pragma unroll
            for (int r = 0; r < RPB; ++r)
                g_A[(row0 + r) * H + hh] =
                    part[0][r][hh] + part[1][r][hh] + b1[hh];
        }
    }
}

// ---------------------------------------------------------------------------
// Stage 2: mma.sync fp16 fused kernel, C-term folded into the weight.
// grid 2048: CTA = (b, s, t-half). 256 threads / 8 warps, 2 CTAs/SM.
// Epilogue gelu packed f32x2 (A-S 7.1.25 3-term erf, sign-folded).
// ---------------------------------------------------------------------------
__device__ __forceinline__ void ldsm_x4(unsigned a, unsigned &r0, unsigned &r1,
                                        unsigned &r2, unsigned &r3) {
    asm volatile("ldmatrix.sync.aligned.m8n8.x4.shared.b16 {%0,%1,%2,%3}, [%4];"
        : "=r"(r0), "=r"(r1), "=r"(r2), "=r"(r3) : "r"(a));
}
__device__ __forceinline__ void ldsm_x4_t(unsigned a, unsigned &r0, unsigned &r1,
                                          unsigned &r2, unsigned &r3) {
    asm volatile("ldmatrix.sync.aligned.m8n8.x4.trans.shared.b16 {%0,%1,%2,%3}, [%4];"
        : "=r"(r0), "=r"(r1), "=r"(r2), "=r"(r3) : "r"(a));
}
__device__ __forceinline__ void mma16816(float* c, const unsigned* a,
                                         unsigned b0, unsigned b1) {
    asm volatile("mma.sync.aligned.m16n8k16.row.col.f32.f16.f16.f32 "
        "{%0,%1,%2,%3}, {%4,%5,%6,%7}, {%8,%9}, {%0,%1,%2,%3};"
        : "+f"(c[0]), "+f"(c[1]), "+f"(c[2]), "+f"(c[3])
        : "r"(a[0]), "r"(a[1]), "r"(a[2]), "r"(a[3]), "r"(b0), "r"(b1));
}
__device__ __forceinline__ void cp16(unsigned dst, const void* src) {
    asm volatile("cp.async.ca.shared.global [%0], [%1], 16;"
        :: "r"(dst), "l"(src) : "memory");
}
__device__ __forceinline__ void cp_commit() {
    asm volatile("cp.async.commit_group;" ::: "memory");
}
__device__ __forceinline__ void cp_wait0() {
    asm volatile("cp.async.wait_group 0;" ::: "memory");
}

// smem byte offsets
#define TROWS 64
#define OFF_WHI 0                          // 128*136*2 = 34816
#define OFF_TH0 34816                      // 64*136*2  = 17408
#define OFF_TH1 52224                      // 17408
#define OFF_SRC 69632                      // 128 f
#define OFF_AS  (OFF_SRC + 512)
#define OFF_W2  (OFF_AS  + 512)
#define OFF_PS  (OFF_W2  + 512)            // 64*4 f
#define SMEM_BYTES (OFF_PS + 1024)

#define NTHR 256

extern __shared__ char smem_raw[];

__global__ __launch_bounds__(NTHR, 2) void edge_main_kernel(
    const float* __restrict__ W1, const float* __restrict__ W2,
    const float* __restrict__ b2p, const int* __restrict__ mask,
    float* __restrict__ out)
{
    __half* Whi = (__half*)(smem_raw + OFF_WHI);
    float* ssrc = (float*)(smem_raw + OFF_SRC);
    float* As   = (float*)(smem_raw + OFF_AS);
    float* w2s  = (float*)(smem_raw + OFF_W2);
    float* psum = (float*)(smem_raw + OFF_PS);     // [64][4]

    unsigned smem_u32;
    asm("{ .reg .u64 t; cvta.to.shared.u64 t, %1; cvt.u32.u64 %0, t; }"
        : "=r"(smem_u32) : "l"(smem_raw));

    const int bs    = blockIdx.x >> 1;       // 0..1023
    const int thalf = blockIdx.x & 1;        // 0 or 1 (t offset 0 / 256)
    const int b     = bs >> 9;
    const int tid   = threadIdx.x;
    const int wid   = tid >> 5;
    const int lane  = tid & 31;

    // Warp tiling within 64t x 128k iteration tile: 2 t-groups x 4 k-groups
    const int tw0 = (wid >> 2) * 32;    // 0 or 32
    const int kq  = (wid & 3) * 32;     // k base
    const int rL = lane & 15;
    const int cL = (lane >> 4) << 3;

    const int gtbase = (b << 9) + thalf * 256;

    // Prefetch Th(0) into buf0 (coalesced 16B cp.async) — overlaps prologue
    {
        const uint4* sth = (const uint4*)(g_th + gtbase * H);
        #pragma unroll
        for (int i = tid; i < TROWS * 16; i += NTHR) {
            const int row = i >> 4;
            const int c8  = i & 15;
            cp16(smem_u32 + OFF_TH0 + (row * PAD + c8 * 8) * 2, sth + i);
        }
        cp_commit();
    }

    if (tid < H) {
        ssrc[tid] = g_src[bs * H + tid];
        As[tid]   = g_A[bs * H + tid];
        w2s[tid]  = W2[tid];
    }
    __syncthreads();

    // Prologue: Whi[h][k] = fp16( src[h]*W1_st[h][k] + W1_t[h][k] ), packed
    {
        const float4* Wst4 = (const float4*)(W1 + 2 * H * H);
        const float4* Wt4  = (const float4*)(W1 + 1 * H * H);
        for (int i = tid; i < (H * H) / 4; i += NTHR) {
            const int h = i >> 5;
            const int c = (i & 31) * 4;
            const u64 sc2 = dup2(ssrc[h]);
            float4 w  = Wst4[i];
            float4 wt = Wt4[i];
            const u64 r01 = f2x_fma(pk2(w.x, w.y), sc2, pk2(wt.x, wt.y));
            const u64 r23 = f2x_fma(pk2(w.z, w.w), sc2, pk2(wt.z, wt.w));
            float f0, f1, f2, f3;
            upk2(f0, f1, r01);
            upk2(f2, f3, r23);
            *(__half2*)(Whi + h * PAD + c)     = __floats2half2_rn(f0, f1);
            *(__half2*)(Whi + h * PAD + c + 2) = __floats2half2_rn(f2, f3);
        }
    }
    __syncthreads();   // As/w2s fully written before register caching

    // Register-cache per-thread A and W2 pairs (packed f32x2, iter-invariant)
    u64 asr2[4], w2r2[4];
    #pragma unroll
    for (int g = 0; g < 4; ++g) {
        const int k = kq + g * 8 + (lane & 3) * 2;
        asr2[g] = pk2(As[k], As[k + 1]);
        w2r2[g] = pk2(w2s[k], w2s[k + 1]);
    }

    // Packed gelu constants (A-S 7.1.25 3-term, sign-folded, negated Horner)
    const u64 C_A  = dup2(0.332676f);       // 0.47047 / sqrt(2)
    const u64 C_1  = dup2(1.0f);
    const u64 C_H  = dup2(0.5f);
    const u64 C_NL = dup2(-0.72134752f);    // -log2(e)/2
    const u64 C_K1 = dup2(-0.7478556f);
    const u64 C_K2 = dup2( 0.0958798f);
    const u64 C_K3 = dup2(-0.3480242f);

    const float b2v  = b2p[0];
    const float mval = mask[bs] ? 1.0f : 0.0f;

    #pragma unroll 1
    for (int tt = 0; tt < 4; ++tt) {
        const int gt0 = gtbase + tt * TROWS;
        const unsigned thb = smem_u32 + ((tt & 1) ? OFF_TH1 : OFF_TH0);

        cp_wait0();          // Th(tt) copies issued by this thread done
        __syncthreads();     // all threads' copies visible

        // Prefetch Th(tt+1) into the other buffer (disjoint from thb)
        if (tt < 3) {
            const unsigned thn = smem_u32 + ((tt & 1) ? OFF_TH0 : OFF_TH1);
            const uint4* sth = (const uint4*)(g_th + (gt0 + TROWS) * H);
            #pragma unroll
            for (int i = tid; i < TROWS * 16; i += NTHR) {
                const int row = i >> 4;
                const int c8  = i & 15;
                cp16(thn + (row * PAD + c8 * 8) * 2, sth + i);
            }
            cp_commit();
        }

        // Mainloop: 32t x 32k per warp, K=128 in 8 steps, single fp16 pass
        float acc[2][4][4];
        #pragma unroll
        for (int f = 0; f < 2; ++f)
            #pragma unroll
            for (int g = 0; g < 4; ++g)
                #pragma unroll
                for (int j = 0; j < 4; ++j) acc[f][g][j] = 0.f;

        #pragma unroll
        for (int step = 0; step < 8; ++step) {
            const int h0 = step * 16;
            unsigned ath[2][4];
            #pragma unroll
            for (int f = 0; f < 2; ++f) {
                unsigned addr = thb + ((tw0 + f * 16 + rL) * PAD + h0 + cL) * 2;
                ldsm_x4(addr, ath[f][0], ath[f][1], ath[f][2], ath[f][3]);
            }
            #pragma unroll
            for (int g = 0; g < 2; ++g) {
                const int nA = kq + g * 16;
                unsigned bh0, bh1, bh2, bh3;
                unsigned baddr = smem_u32 + OFF_WHI + ((h0 + rL) * PAD + nA + cL) * 2;
                ldsm_x4_t(baddr, bh0, bh1, bh2, bh3);
                #pragma unroll
                for (int f = 0; f < 2; ++f) {
                    mma16816(acc[f][2 * g],     ath[f], bh0, bh1);
                    mma16816(acc[f][2 * g + 1], ath[f], bh2, bh3);
                }
            }
        }

        // Epilogue: packed f32x2 gelu + W2-dot, quad-reduce, psum, softsign.
        // gelu(x) = 0.5x + q + q*(P(t)*e), q=0.5|x|, t=1/(1+p|x|/sqrt2),
        //           e=2^(-x^2*log2e/2), P = negated 3-term A-S Horner.
        #pragma unroll
        for (int f = 0; f < 2; ++f) {
            #pragma unroll
            for (int hf = 0; hf < 2; ++hf) {
                const int t = tw0 + f * 16 + (lane >> 2) + hf * 8;
                u64 pt2 = 0ULL;
                #pragma unroll
                for (int g = 0; g < 4; ++g) {
                    u64 x2 = pk2(acc[f][g][hf * 2 + 0], acc[f][g][hf * 2 + 1]);
                    x2 = f2x_add(x2, asr2[g]);
                    const u64 ax2 = x2 & 0x7FFFFFFF7FFFFFFFULL;
                    const u64 d2 = f2x_fma(C_A, ax2, C_1);
                    const u64 s2 = f2x_mul(ax2, ax2);
                    const u64 y2 = f2x_mul(s2, C_NL);
                    float dl, dh;  upk2(dl, dh, d2);
                    const u64 t2 = pk2(rcp_ap(dl), rcp_ap(dh));
                    float yl, yh;  upk2(yl, yh, y2);
                    const u64 e2 = pk2(ex2_ap(yl), ex2_ap(yh));
                    u64 p2 = f2x_fma(C_K1, t2, C_K2);
                    p2 = f2x_fma(p2, t2, C_K3);
                    p2 = f2x_mul(p2, t2);
                    const u64 m2 = f2x_mul(p2, e2);
                    const u64 q2 = f2x_mul(ax2, C_H);
                    const u64 bb = f2x_fma(x2, C_H, q2);
                    const u64 r2 = f2x_fma(m2, q2, bb);
                    pt2 = f2x_fma(r2, w2r2[g], pt2);
                }
                float plo, phi; upk2(plo, phi, pt2);
                float pt = plo + phi;
                pt += __shfl_xor_sync(0xffffffffu, pt, 1);
                pt += __shfl_xor_sync(0xffffffffu, pt, 2);
                if ((lane & 3) == 0)
                    psum[t * 4 + (wid & 3)] = pt;
            }
        }
        __syncthreads();

        if (tid < TROWS) {
            const float sc = psum[tid * 4] + psum[tid * 4 + 1]
                           + psum[tid * 4 + 2] + psum[tid * 4 + 3] + b2v;
            const float e  = sc / (1.0f + fabsf(sc));
            out[bs * T + thalf * 256 + tt * TROWS + tid] = e * mval;
        }
    }
}

// ---------------------------------------------------------------------------
extern "C" void kernel_launch(void* const* d_in, const int* in_sizes, int n_in,
                              void* d_out, int out_size)
{
    const float* sv   = (const float*)d_in[0];
    const float* tv   = (const float*)d_in[1];
    const int*   mask = (const int*)d_in[2];
    const float* sng  = (const float*)d_in[3];
    const float* snb  = (const float*)d_in[4];
    const float* tng  = (const float*)d_in[5];
    const float* tnb  = (const float*)d_in[6];
    const float* Wsu  = (const float*)d_in[7];
    const float* bsu  = (const float*)d_in[8];
    const float* Wtp  = (const float*)d_in[9];
    const float* btp  = (const float*)d_in[10];
    const float* W1   = (const float*)d_in[11];
    const float* b1   = (const float*)d_in[12];
    const float* W2   = (const float*)d_in[13];
    const float* b2   = (const float*)d_in[14];
    float* out = (float*)d_out;

    norm_proj_kernel<<<(BS + BT) / RPB, 256>>>(sv, tv, sng, snb, tng, tnb,
                                               Wsu, bsu, Wtp, btp, W1, b1);

    cudaFuncSetAttribute(edge_main_kernel,
                         cudaFuncAttributeMaxDynamicSharedMemorySize, SMEM_BYTES);
    edge_main_kernel<<<2 * BS, NTHR, SMEM_BYTES>>>(W1, W2, b2, mask, out);
}